// round 1
// baseline (speedup 1.0000x reference)
#include <cuda_runtime.h>
#include <cuda_bf16.h>
#include <math.h>

// Problem constants
#define BATCH 4
#define SEQ   2048
#define DIM   1024
#define HEADS 16
#define DH    64
#define NF    64
#define NBH   (BATCH*HEADS)          // 64
#define ROWS  (NBH*SEQ)              // 131072 head-rows
#define MROWS (BATCH*SEQ)            // 8192 GEMM rows
#define CH    64                     // chunk length
#define NCHUNK (SEQ/CH)              // 32
#define PAD   68                     // smem row pad (float4-aligned, conflict-free)

// ---------------- device scratch ----------------
__device__ float g_Q[ROWS*DH];
__device__ float g_K[ROWS*DH];
__device__ float g_V[ROWS*DH];
__device__ float g_phiq[ROWS*NF];
__device__ float g_phik[ROWS*NF];
__device__ float g_attn[MROWS*DIM];
__device__ float g_kv[NBH*NCHUNK*NF*DH];   // per-chunk KV state -> exclusive prefix (in place)
__device__ float g_ks[NBH*NCHUNK*NF];      // per-chunk k-sum    -> exclusive prefix (in place)

// ---------------- SGEMM: C[M,N] = A[M,K] @ B[N,K]^T  (all row-major) ----------------
// 128x128 tile, K-step 8, 256 threads, 8x8 micro-tile.
__global__ __launch_bounds__(256) void sgemm_nt(const float* __restrict__ A,
                                                const float* __restrict__ B,
                                                float* __restrict__ C,
                                                int M, int N, int K)
{
    __shared__ float As[8][128];
    __shared__ float Bs[8][128];
    const int t  = threadIdx.x;
    const int bm = blockIdx.y * 128;
    const int bn = blockIdx.x * 128;
    const int lr = t >> 1;           // 0..127
    const int lc = (t & 1) * 4;      // 0 or 4
    const int tx = t & 15;
    const int ty = t >> 4;

    const float* Ag = A + (size_t)(bm + lr) * K + lc;
    const float* Bg = B + (size_t)(bn + lr) * K + lc;

    float acc[8][8];
#pragma unroll
    for (int i = 0; i < 8; i++)
#pragma unroll
        for (int j = 0; j < 8; j++) acc[i][j] = 0.f;

    for (int k0 = 0; k0 < K; k0 += 8) {
        float4 av = *(const float4*)(Ag + k0);
        float4 bv = *(const float4*)(Bg + k0);
        __syncthreads();
        As[lc+0][lr] = av.x; As[lc+1][lr] = av.y; As[lc+2][lr] = av.z; As[lc+3][lr] = av.w;
        Bs[lc+0][lr] = bv.x; Bs[lc+1][lr] = bv.y; Bs[lc+2][lr] = bv.z; Bs[lc+3][lr] = bv.w;
        __syncthreads();
#pragma unroll
        for (int kk = 0; kk < 8; kk++) {
            float a[8], b[8];
            *(float4*)(a)   = *(const float4*)&As[kk][ty*8];
            *(float4*)(a+4) = *(const float4*)&As[kk][ty*8+4];
            *(float4*)(b)   = *(const float4*)&Bs[kk][tx*8];
            *(float4*)(b+4) = *(const float4*)&Bs[kk][tx*8+4];
#pragma unroll
            for (int i = 0; i < 8; i++)
#pragma unroll
                for (int j = 0; j < 8; j++)
                    acc[i][j] += a[i] * b[j];
        }
    }
#pragma unroll
    for (int i = 0; i < 8; i++) {
        float* Cr = C + (size_t)(bm + ty*8 + i) * N + bn + tx*8;
        *(float4*)(Cr)   = make_float4(acc[i][0], acc[i][1], acc[i][2], acc[i][3]);
        *(float4*)(Cr+4) = make_float4(acc[i][4], acc[i][5], acc[i][6], acc[i][7]);
    }
}

// ---------------- feature map ----------------
// phi = f^{-1/2} * ( exp( dn*(q . proj_f) [- rowmax] - ||q||^2/128 ) + 1e-4 )
// one warp per row; proj held transposed in smem.
__global__ __launch_bounds__(256) void feature_kernel(const float* __restrict__ X,
                                                      const float* __restrict__ proj,
                                                      float* __restrict__ phi,
                                                      int is_query)
{
    __shared__ float pT[64*64];
    __shared__ float qs[8][64];
    const int t = threadIdx.x;
    for (int i = t; i < 4096; i += 256) {
        int f_ = i >> 6, d_ = i & 63;
        pT[d_*64 + f_] = proj[i];
    }
    const int w = t >> 5, l = t & 31;
    const size_t row = (size_t)blockIdx.x * 8 + w;
    const float* xr = X + row * 64;
    qs[w][l]      = xr[l];
    qs[w][l + 32] = xr[l + 32];
    __syncthreads();

    float q0 = qs[w][l], q1 = qs[w][l+32];
    float sq = q0*q0 + q1*q1;
#pragma unroll
    for (int o = 16; o >= 1; o >>= 1) sq += __shfl_xor_sync(0xffffffffu, sq, o);
    const float diag = sq * (1.0f/128.0f);

    float dd0 = 0.f, dd1 = 0.f;
#pragma unroll
    for (int d = 0; d < 64; d++) {
        float qd = qs[w][d];
        dd0 += qd * pT[d*64 + l];
        dd1 += qd * pT[d*64 + l + 32];
    }
    const float dn = 0.35355339059327373f;   // 64^{-1/4}
    dd0 *= dn; dd1 *= dn;
    if (is_query) {
        float mx = fmaxf(dd0, dd1);
#pragma unroll
        for (int o = 16; o >= 1; o >>= 1) mx = fmaxf(mx, __shfl_xor_sync(0xffffffffu, mx, o));
        dd0 -= mx; dd1 -= mx;
    }
    phi[row*64 + l]      = 0.125f * (expf(dd0 - diag) + 1e-4f);
    phi[row*64 + l + 32] = 0.125f * (expf(dd1 - diag) + 1e-4f);
}

// ---------------- per-chunk local states: KVloc = K^T V (64x64), kloc = sum k ----------------
__global__ __launch_bounds__(256) void chunk_local_kernel(const float* __restrict__ phiK,
                                                          const float* __restrict__ V,
                                                          float* __restrict__ kvloc,
                                                          float* __restrict__ kloc)
{
    __shared__ float ks[16*64];
    __shared__ float vs[16*64];
    const int t = threadIdx.x;
    const int chunk = blockIdx.x, bh = blockIdx.y;
    const size_t base = ((size_t)bh * SEQ + chunk * CH) * 64;
    const int f = t >> 2, c0 = t & 3;

    float acc[16];
#pragma unroll
    for (int m = 0; m < 16; m++) acc[m] = 0.f;
    float kl = 0.f;

    for (int st = 0; st < 4; st++) {
        __syncthreads();
        {
            int r = t >> 4, c4 = (t & 15) << 2;
            *(float4*)&ks[r*64 + c4] = *(const float4*)(phiK + base + (size_t)(st*16 + r)*64 + c4);
            *(float4*)&vs[r*64 + c4] = *(const float4*)(V    + base + (size_t)(st*16 + r)*64 + c4);
        }
        __syncthreads();
#pragma unroll
        for (int r = 0; r < 16; r++) {
            float kv = ks[r*64 + f];
#pragma unroll
            for (int m = 0; m < 16; m++) acc[m] += kv * vs[r*64 + c0 + 4*m];
        }
        if (t < 64) {
#pragma unroll
            for (int r = 0; r < 16; r++) kl += ks[r*64 + t];
        }
    }
    const size_t ob = ((size_t)bh * NCHUNK + chunk) * (64*64);
#pragma unroll
    for (int m = 0; m < 16; m++) kvloc[ob + (size_t)f*64 + c0 + 4*m] = acc[m];
    if (t < 64) kloc[((size_t)bh * NCHUNK + chunk) * 64 + t] = kl;
}

// ---------------- exclusive prefix across chunks (per bh) ----------------
__global__ __launch_bounds__(256) void prefix_kernel(float* __restrict__ kvloc,
                                                     float* __restrict__ kloc)
{
    const int bh = blockIdx.x;
    const int t = threadIdx.x;
    float run[16];
#pragma unroll
    for (int m = 0; m < 16; m++) run[m] = 0.f;
    for (int c = 0; c < NCHUNK; c++) {
        const size_t b = ((size_t)bh * NCHUNK + c) * 4096;
#pragma unroll
        for (int m = 0; m < 16; m++) {
            float v = kvloc[b + t + 256*m];
            kvloc[b + t + 256*m] = run[m];
            run[m] += v;
        }
    }
    if (t < 64) {
        float rk = 0.f;
        for (int c = 0; c < NCHUNK; c++) {
            const size_t b = ((size_t)bh * NCHUNK + c) * 64 + t;
            float v = kloc[b];
            kloc[b] = rk;
            rk += v;
        }
    }
}

// ---------------- per-chunk output + Wpost + head-transpose store ----------------
// O = masked(Q K^T) V + Q @ KVprev ; denom = rowsum(masked S) + q.kprev (clamped)
// then (O/denom) @ Wpost^T written to attn[b, s, h*64+e]
__global__ __launch_bounds__(256) void chunk_out_kernel(const float* __restrict__ phiQ,
                                                        const float* __restrict__ phiK,
                                                        const float* __restrict__ Vg,
                                                        const float* __restrict__ KVp,
                                                        const float* __restrict__ Kp,
                                                        const float* __restrict__ Wpost,
                                                        float* __restrict__ attn)
{
    extern __shared__ float sm[];
    float* Qs  = sm;                 // 64*PAD
    float* Ks  = Qs  + 64*PAD;
    float* Vs  = Ks  + 64*PAD;
    float* Ss  = Vs  + 64*PAD;       // S then reused for O/denom
    float* KVs = Ss  + 64*PAD;
    float* Wps = KVs + 64*PAD;       // Wpost transposed [c][e]
    float* den = Wps + 64*PAD;       // 64
    float* kps = den + 64;           // 64

    const int t = threadIdx.x;
    const int chunk = blockIdx.x, bh = blockIdx.y;
    const size_t base   = ((size_t)bh * SEQ + chunk * CH) * 64;
    const size_t kvbase = ((size_t)bh * NCHUNK + chunk) * 4096;

    for (int i = t; i < 1024; i += 256) {          // 1024 float4's per 64x64 tile
        int r = i >> 4, c4 = (i & 15) << 2;
        *(float4*)&Qs [r*PAD + c4] = *(const float4*)(phiQ + base   + (size_t)r*64 + c4);
        *(float4*)&Ks [r*PAD + c4] = *(const float4*)(phiK + base   + (size_t)r*64 + c4);
        *(float4*)&Vs [r*PAD + c4] = *(const float4*)(Vg   + base   + (size_t)r*64 + c4);
        *(float4*)&KVs[r*PAD + c4] = *(const float4*)(KVp  + kvbase + (size_t)r*64 + c4);
    }
    for (int i = t; i < 4096; i += 256) {          // transpose Wpost
        int e = i >> 6, c = i & 63;
        Wps[c*PAD + e] = Wpost[i];
    }
    if (t < 64) kps[t] = Kp[((size_t)bh * NCHUNK + chunk) * 64 + t];
    __syncthreads();

    const int r  = t >> 2;
    const int c0 = t & 3;

    // ---- S = Q K^T (this thread: row r, cols c0+4m) ----
    float sacc[16];
#pragma unroll
    for (int m = 0; m < 16; m++) sacc[m] = 0.f;
#pragma unroll
    for (int d = 0; d < 64; d += 4) {
        float4 q4 = *(const float4*)&Qs[r*PAD + d];
#pragma unroll
        for (int m = 0; m < 16; m++) {
            int j = c0 + 4*m;
            float4 k4 = *(const float4*)&Ks[j*PAD + d];
            sacc[m] += q4.x*k4.x + q4.y*k4.y + q4.z*k4.z + q4.w*k4.w;
        }
    }
    // ---- mask + rowsum + denominator ----
    float rs = 0.f;
#pragma unroll
    for (int m = 0; m < 16; m++) {
        int j = c0 + 4*m;
        float sv = (j <= r) ? sacc[m] : 0.f;
        Ss[r*PAD + j] = sv;
        rs += sv;
    }
    float qk = 0.f;
#pragma unroll
    for (int m = 0; m < 16; m++) {
        int c = c0 + 4*m;
        qk += Qs[r*PAD + c] * kps[c];
    }
    float dp = rs + qk;
    dp += __shfl_xor_sync(0xffffffffu, dp, 1);
    dp += __shfl_xor_sync(0xffffffffu, dp, 2);
    if (c0 == 0) den[r] = fmaxf(dp, 1e-6f);
    __syncthreads();

    // ---- O = S V + Q KVprev ----
    float oacc[16];
#pragma unroll
    for (int m = 0; m < 16; m++) oacc[m] = 0.f;
#pragma unroll
    for (int j = 0; j < 64; j += 4) {
        float4 s4 = *(const float4*)&Ss[r*PAD + j];
#pragma unroll
        for (int m = 0; m < 16; m++) {
            int c = c0 + 4*m;
            oacc[m] += s4.x*Vs[(j+0)*PAD + c] + s4.y*Vs[(j+1)*PAD + c]
                     + s4.z*Vs[(j+2)*PAD + c] + s4.w*Vs[(j+3)*PAD + c];
        }
    }
#pragma unroll
    for (int f = 0; f < 64; f += 4) {
        float4 q4 = *(const float4*)&Qs[r*PAD + f];
#pragma unroll
        for (int m = 0; m < 16; m++) {
            int c = c0 + 4*m;
            oacc[m] += q4.x*KVs[(f+0)*PAD + c] + q4.y*KVs[(f+1)*PAD + c]
                     + q4.z*KVs[(f+2)*PAD + c] + q4.w*KVs[(f+3)*PAD + c];
        }
    }
    const float inv = 1.0f / den[r];
#pragma unroll
    for (int m = 0; m < 16; m++) oacc[m] *= inv;
    __syncthreads();                 // done reading Ss as S
#pragma unroll
    for (int m = 0; m < 16; m++) Ss[r*PAD + c0 + 4*m] = oacc[m];   // Ss now holds O/denom
    __syncthreads();

    // ---- epilogue: (O/denom) @ Wpost^T ----
    float facc[16];
#pragma unroll
    for (int m = 0; m < 16; m++) facc[m] = 0.f;
#pragma unroll
    for (int c = 0; c < 64; c += 4) {
        float4 o4 = *(const float4*)&Ss[r*PAD + c];
#pragma unroll
        for (int m = 0; m < 16; m++) {
            int e = c0 + 4*m;
            facc[m] += o4.x*Wps[(c+0)*PAD + e] + o4.y*Wps[(c+1)*PAD + e]
                     + o4.z*Wps[(c+2)*PAD + e] + o4.w*Wps[(c+3)*PAD + e];
        }
    }
    const int bi = bh >> 4, hi = bh & 15;
    const int si = chunk * CH + r;
    float* dst = attn + ((size_t)bi * SEQ + si) * DIM + hi * 64;
#pragma unroll
    for (int m = 0; m < 16; m++) dst[c0 + 4*m] = facc[m];
}

// ---------------- launch ----------------
extern "C" void kernel_launch(void* const* d_in, const int* in_sizes, int n_in,
                              void* d_out, int out_size)
{
    const float* x     = (const float*)d_in[0];
    const float* Wq    = (const float*)d_in[1];
    const float* Wk    = (const float*)d_in[2];
    const float* Wv    = (const float*)d_in[3];
    const float* proj  = (const float*)d_in[4];
    const float* Wpost = (const float*)d_in[5];
    const float* Wout  = (const float*)d_in[6];
    float* out = (float*)d_out;

    float *pQ, *pK, *pV, *pphiq, *pphik, *pattn, *pkv, *pks;
    cudaGetSymbolAddress((void**)&pQ, g_Q);
    cudaGetSymbolAddress((void**)&pK, g_K);
    cudaGetSymbolAddress((void**)&pV, g_V);
    cudaGetSymbolAddress((void**)&pphiq, g_phiq);
    cudaGetSymbolAddress((void**)&pphik, g_phik);
    cudaGetSymbolAddress((void**)&pattn, g_attn);
    cudaGetSymbolAddress((void**)&pkv, g_kv);
    cudaGetSymbolAddress((void**)&pks, g_ks);

    static const size_t chunk_smem = (size_t)(6*64*PAD + 128) * sizeof(float);
    cudaFuncSetAttribute(chunk_out_kernel, cudaFuncAttributeMaxDynamicSharedMemorySize,
                         (int)chunk_smem);

    dim3 gg(DIM/128, MROWS/128);     // (8, 64)

    // Q/K/V projections
    sgemm_nt<<<gg, 256>>>(x, Wq, pQ, MROWS, DIM, DIM);
    sgemm_nt<<<gg, 256>>>(x, Wk, pK, MROWS, DIM, DIM);
    sgemm_nt<<<gg, 256>>>(x, Wv, pV, MROWS, DIM, DIM);

    // feature maps
    feature_kernel<<<ROWS/8, 256>>>(pQ, proj, pphiq, 1);
    feature_kernel<<<ROWS/8, 256>>>(pK, proj, pphik, 0);

    // chunked causal linear attention
    dim3 gc(NCHUNK, NBH);            // (32, 64)
    chunk_local_kernel<<<gc, 256>>>(pphik, pV, pkv, pks);
    prefix_kernel<<<NBH, 256>>>(pkv, pks);
    chunk_out_kernel<<<gc, 256, chunk_smem>>>(pphiq, pphik, pV, pkv, pks, Wpost, pattn);

    // final output projection
    sgemm_nt<<<gg, 256>>>(pattn, Wout, out, MROWS, DIM, DIM);
}

// round 4
// speedup vs baseline: 2.2537x; 2.2537x over previous
#include <cuda_runtime.h>
#include <cuda_bf16.h>
#include <math.h>
#include <cstdint>

// Problem constants
#define BATCH 4
#define SEQ   2048
#define DIM   1024
#define HEADS 16
#define DH    64
#define NF    64
#define NBH   (BATCH*HEADS)          // 64
#define ROWS  (NBH*SEQ)              // 131072 head-rows
#define MROWS (BATCH*SEQ)            // 8192 GEMM rows
#define CH    64                     // chunk length
#define NCHUNK (SEQ/CH)              // 32
#define PAD   68

// ---------------- device scratch ----------------
__device__ float g_Q[ROWS*DH];
__device__ float g_K[ROWS*DH];
__device__ float g_V[ROWS*DH];
__device__ float g_phiq[ROWS*NF];
__device__ float g_phik[ROWS*NF];
__device__ float g_attn[MROWS*DIM];
__device__ float g_kv[NBH*NCHUNK*NF*DH];
__device__ float g_ks[NBH*NCHUNK*NF];
// bf16 split buffers
__device__ __nv_bfloat16 g_xhi[MROWS*DIM];
__device__ __nv_bfloat16 g_xlo[MROWS*DIM];
__device__ __nv_bfloat16 g_ahi[MROWS*DIM];
__device__ __nv_bfloat16 g_alo[MROWS*DIM];
__device__ __nv_bfloat16 g_whi[4*DIM*DIM];
__device__ __nv_bfloat16 g_wlo[4*DIM*DIM];

// ================= helpers =================
__device__ __forceinline__ uint32_t smem_u32(const void* p) {
    uint32_t a;
    asm("{ .reg .u64 tmp; cvta.to.shared.u64 tmp, %1; cvt.u32.u64 %0, tmp; }" : "=r"(a) : "l"(p));
    return a;
}
__device__ __forceinline__ void ldm_x4(uint32_t* r, uint32_t addr) {
    asm volatile("ldmatrix.sync.aligned.m8n8.x4.shared.b16 {%0,%1,%2,%3}, [%4];"
        : "=r"(r[0]), "=r"(r[1]), "=r"(r[2]), "=r"(r[3]) : "r"(addr));
}
__device__ __forceinline__ void mma_bf16(float* d, const uint32_t* a, const uint32_t* b) {
    asm volatile("mma.sync.aligned.m16n8k16.row.col.f32.bf16.bf16.f32 "
        "{%0,%1,%2,%3}, {%4,%5,%6,%7}, {%8,%9}, {%0,%1,%2,%3};"
        : "+f"(d[0]), "+f"(d[1]), "+f"(d[2]), "+f"(d[3])
        : "r"(a[0]), "r"(a[1]), "r"(a[2]), "r"(a[3]), "r"(b[0]), "r"(b[1]));
}

// ================= split conversion =================
__global__ __launch_bounds__(256) void convert_split(const float* __restrict__ s,
                                                     __nv_bfloat16* __restrict__ hi,
                                                     __nv_bfloat16* __restrict__ lo, int n4)
{
    int i = blockIdx.x * 256 + threadIdx.x;
    if (i >= n4) return;
    float4 v = ((const float4*)s)[i];
    __nv_bfloat16 h0 = __float2bfloat16(v.x);
    __nv_bfloat16 h1 = __float2bfloat16(v.y);
    __nv_bfloat16 h2 = __float2bfloat16(v.z);
    __nv_bfloat16 h3 = __float2bfloat16(v.w);
    __nv_bfloat16 l0 = __float2bfloat16(v.x - __bfloat162float(h0));
    __nv_bfloat16 l1 = __float2bfloat16(v.y - __bfloat162float(h1));
    __nv_bfloat16 l2 = __float2bfloat16(v.z - __bfloat162float(h2));
    __nv_bfloat16 l3 = __float2bfloat16(v.w - __bfloat162float(h3));
    __nv_bfloat162 p;
    p.x = h0; p.y = h1; ((__nv_bfloat162*)hi)[2*i]   = p;
    p.x = h2; p.y = h3; ((__nv_bfloat162*)hi)[2*i+1] = p;
    p.x = l0; p.y = l1; ((__nv_bfloat162*)lo)[2*i]   = p;
    p.x = l2; p.y = l3; ((__nv_bfloat162*)lo)[2*i+1] = p;
}

// ================= HMMA split-bf16 GEMM =================
// C[M,N] = A[M,K] @ B[N,K]^T with A=Ahi+Alo, B=Bhi+Blo (drop lo*lo), fp32 accum.
// 128x128 CTA tile, 8 warps (2x4), warp tile 64x32, k-slab 32, double buffer.
#define ASTR 40                        // smem row stride in bf16 (80 B, ldmatrix conflict-free)
#define TILE_SMEM (128*ASTR*2)         // 10240 B per 128x32 tile
#define BUFB (4*TILE_SMEM)             // Ahi,Alo,Bhi,Blo per buffer

__global__ __launch_bounds__(256) void gemm_hmma_split(
    const __nv_bfloat16* __restrict__ Ahi, const __nv_bfloat16* __restrict__ Alo,
    const __nv_bfloat16* __restrict__ Bhi, const __nv_bfloat16* __restrict__ Blo,
    float* __restrict__ C, int M, int N, int K)
{
    extern __shared__ char smx[];
    const int t = threadIdx.x;
    const int wid = t >> 5, lane = t & 31;
    const int wm = wid >> 2, wn = wid & 3;
    const int bm = blockIdx.y * 128, bn = blockIdx.x * 128;

    float acc[4][4][4];
#pragma unroll
    for (int i = 0; i < 4; i++)
#pragma unroll
        for (int j = 0; j < 4; j++)
#pragma unroll
            for (int q = 0; q < 4; q++) acc[i][j][q] = 0.f;

    const __nv_bfloat16* srcs[4] = {Ahi, Alo, Bhi, Blo};
    float4 stg[8];

    // ---- global load of slab s into staging regs ----
    auto gload = [&](int s) {
        const int k0 = s * 32;
#pragma unroll
        for (int q = 0; q < 8; q++) {
            int tile = q >> 1;
            int i = (q & 1) * 256 + t;         // 0..511
            int r = i >> 2, ch = i & 3;
            int rb = (tile < 2) ? bm : bn;
            stg[q] = *(const float4*)(srcs[tile] + (size_t)(rb + r) * K + k0 + ch * 8);
        }
    };
    // ---- staging regs -> smem buffer b ----
    auto sstore = [&](int b) {
#pragma unroll
        for (int q = 0; q < 8; q++) {
            int tile = q >> 1;
            int i = (q & 1) * 256 + t;
            int r = i >> 2, ch = i & 3;
            *(float4*)(smx + b * BUFB + tile * TILE_SMEM + r * 80 + ch * 16) = stg[q];
        }
    };
    // ---- compute one k-slab from buffer b ----
    auto compute = [&](int b) {
        const char* Ahb = smx + b * BUFB;
        const char* Alb = Ahb + TILE_SMEM;
        const char* Bhb = Ahb + 2 * TILE_SMEM;
        const char* Blb = Ahb + 3 * TILE_SMEM;
        const int lrA = lane & 15, kbA = lane >> 4;                    // A ldmatrix lanes
        const int nrB = (lane & 7) + ((lane >> 4) << 3);               // B ldmatrix lanes
        const int kbB = (lane >> 3) & 1;
#pragma unroll
        for (int ks = 0; ks < 2; ks++) {
            uint32_t ah[4][4], al[4][4];
#pragma unroll
            for (int ma = 0; ma < 4; ma++) {
                uint32_t off = (uint32_t)((wm * 64 + ma * 16 + lrA) * 80 + ks * 32 + kbA * 16);
                ldm_x4(ah[ma], smem_u32(Ahb + off));
                ldm_x4(al[ma], smem_u32(Alb + off));
            }
            uint32_t bh[4][2], bl[4][2];
#pragma unroll
            for (int np = 0; np < 2; np++) {
                uint32_t off = (uint32_t)((wn * 32 + np * 16 + nrB) * 80 + ks * 32 + kbB * 16);
                uint32_t tmp[4];
                ldm_x4(tmp, smem_u32(Bhb + off));
                bh[2*np][0] = tmp[0]; bh[2*np][1] = tmp[1];
                bh[2*np+1][0] = tmp[2]; bh[2*np+1][1] = tmp[3];
                ldm_x4(tmp, smem_u32(Blb + off));
                bl[2*np][0] = tmp[0]; bl[2*np][1] = tmp[1];
                bl[2*np+1][0] = tmp[2]; bl[2*np+1][1] = tmp[3];
            }
#pragma unroll
            for (int ma = 0; ma < 4; ma++)
#pragma unroll
                for (int na = 0; na < 4; na++) {
                    mma_bf16(acc[ma][na], ah[ma], bh[na]);
                    mma_bf16(acc[ma][na], ah[ma], bl[na]);
                    mma_bf16(acc[ma][na], al[ma], bh[na]);
                }
        }
    };

    const int S = K / 32;
    gload(0); sstore(0);
    __syncthreads();
    for (int s = 0; s < S; s++) {
        if (s + 1 < S) gload(s + 1);
        compute(s & 1);
        if (s + 1 < S) sstore((s + 1) & 1);
        __syncthreads();
    }

    // ---- epilogue ----
    const int g = lane >> 2, tig = lane & 3;
#pragma unroll
    for (int ma = 0; ma < 4; ma++) {
        const int r0 = bm + wm * 64 + ma * 16 + g;
#pragma unroll
        for (int na = 0; na < 4; na++) {
            const int c = bn + wn * 32 + na * 8 + tig * 2;
            *(float2*)(C + (size_t)r0 * N + c)       = make_float2(acc[ma][na][0], acc[ma][na][1]);
            *(float2*)(C + (size_t)(r0 + 8) * N + c) = make_float2(acc[ma][na][2], acc[ma][na][3]);
        }
    }
}

// ================= feature map (register-tiled 64x64 mini-GEMM) =================
__global__ __launch_bounds__(256) void feature_kernel(const float* __restrict__ X,
                                                      const float* __restrict__ proj,
                                                      float* __restrict__ phi,
                                                      int is_query)
{
    __shared__ float XsT[64*PAD];   // [d][r]
    __shared__ float pT[64*PAD];    // [d][f]
    const int t = threadIdx.x;
    const size_t base = (size_t)blockIdx.x * 64 * 64;

    for (int i = t; i < 4096; i += 256) { int f_ = i >> 6, d_ = i & 63; pT[d_*PAD + f_] = proj[i]; }
    for (int i = t; i < 4096; i += 256) { int r_ = i >> 6, d_ = i & 63; XsT[d_*PAD + r_] = X[base + i]; }
    __syncthreads();

    const int r0 = (t >> 4) << 2;
    const int f0 = (t & 15) << 2;
    float acc[4][4], sq[4];
#pragma unroll
    for (int i = 0; i < 4; i++) { sq[i] = 0.f;
#pragma unroll
        for (int j = 0; j < 4; j++) acc[i][j] = 0.f; }

#pragma unroll
    for (int d = 0; d < 64; d++) {
        float4 a = *(const float4*)&XsT[d*PAD + r0];
        float4 b = *(const float4*)&pT[d*PAD + f0];
        float av[4] = {a.x, a.y, a.z, a.w};
        float bv[4] = {b.x, b.y, b.z, b.w};
#pragma unroll
        for (int i = 0; i < 4; i++) {
            sq[i] += av[i] * av[i];
#pragma unroll
            for (int j = 0; j < 4; j++) acc[i][j] += av[i] * bv[j];
        }
    }
    const float dn = 0.35355339059327373f;   // 64^{-1/4}
    float dd[4][4];
#pragma unroll
    for (int i = 0; i < 4; i++)
#pragma unroll
        for (int j = 0; j < 4; j++) dd[i][j] = dn * acc[i][j];

    if (is_query) {
#pragma unroll
        for (int i = 0; i < 4; i++) {
            float mx = fmaxf(fmaxf(dd[i][0], dd[i][1]), fmaxf(dd[i][2], dd[i][3]));
#pragma unroll
            for (int o = 8; o >= 1; o >>= 1) mx = fmaxf(mx, __shfl_xor_sync(0xffffffffu, mx, o));
#pragma unroll
            for (int j = 0; j < 4; j++) dd[i][j] -= mx;
        }
    }
#pragma unroll
    for (int i = 0; i < 4; i++) {
        const float diag = sq[i] * (1.0f / 128.0f);
        float4 o;
        o.x = 0.125f * (expf(dd[i][0] - diag) + 1e-4f);
        o.y = 0.125f * (expf(dd[i][1] - diag) + 1e-4f);
        o.z = 0.125f * (expf(dd[i][2] - diag) + 1e-4f);
        o.w = 0.125f * (expf(dd[i][3] - diag) + 1e-4f);
        *(float4*)&phi[((size_t)blockIdx.x * 64 + r0 + i) * 64 + f0] = o;
    }
}

// ================= chunk kernels =================
__global__ __launch_bounds__(256) void chunk_local_kernel(const float* __restrict__ phiK,
                                                          const float* __restrict__ V,
                                                          float* __restrict__ kvloc,
                                                          float* __restrict__ kloc)
{
    __shared__ float ks[16*64];
    __shared__ float vs[16*64];
    const int t = threadIdx.x;
    const int chunk = blockIdx.x, bh = blockIdx.y;
    const size_t base = ((size_t)bh * SEQ + chunk * CH) * 64;
    const int f = t >> 2, c0 = t & 3;

    float acc[16];
#pragma unroll
    for (int m = 0; m < 16; m++) acc[m] = 0.f;
    float kl = 0.f;

    for (int st = 0; st < 4; st++) {
        __syncthreads();
        {
            int r = t >> 4, c4 = (t & 15) << 2;
            *(float4*)&ks[r*64 + c4] = *(const float4*)(phiK + base + (size_t)(st*16 + r)*64 + c4);
            *(float4*)&vs[r*64 + c4] = *(const float4*)(V    + base + (size_t)(st*16 + r)*64 + c4);
        }
        __syncthreads();
#pragma unroll
        for (int r = 0; r < 16; r++) {
            float kv = ks[r*64 + f];
#pragma unroll
            for (int m = 0; m < 16; m++) acc[m] += kv * vs[r*64 + c0 + 4*m];
        }
        if (t < 64) {
#pragma unroll
            for (int r = 0; r < 16; r++) kl += ks[r*64 + t];
        }
    }
    const size_t ob = ((size_t)bh * NCHUNK + chunk) * (64*64);
#pragma unroll
    for (int m = 0; m < 16; m++) kvloc[ob + (size_t)f*64 + c0 + 4*m] = acc[m];
    if (t < 64) kloc[((size_t)bh * NCHUNK + chunk) * 64 + t] = kl;
}

__global__ __launch_bounds__(256) void prefix_kernel(float* __restrict__ kvloc,
                                                     float* __restrict__ kloc)
{
    const int bh = blockIdx.x;
    const int t = threadIdx.x;
    float run[16];
#pragma unroll
    for (int m = 0; m < 16; m++) run[m] = 0.f;
    for (int c = 0; c < NCHUNK; c++) {
        const size_t b = ((size_t)bh * NCHUNK + c) * 4096;
#pragma unroll
        for (int m = 0; m < 16; m++) {
            float v = kvloc[b + t + 256*m];
            kvloc[b + t + 256*m] = run[m];
            run[m] += v;
        }
    }
    if (t < 64) {
        float rk = 0.f;
        for (int c = 0; c < NCHUNK; c++) {
            const size_t b = ((size_t)bh * NCHUNK + c) * 64 + t;
            float v = kloc[b];
            kloc[b] = rk;
            rk += v;
        }
    }
}

__global__ __launch_bounds__(256) void chunk_out_kernel(const float* __restrict__ phiQ,
                                                        const float* __restrict__ phiK,
                                                        const float* __restrict__ Vg,
                                                        const float* __restrict__ KVp,
                                                        const float* __restrict__ Kp,
                                                        const float* __restrict__ Wpost,
                                                        float* __restrict__ attn)
{
    extern __shared__ float sm[];
    float* Qs  = sm;
    float* Ks  = Qs  + 64*PAD;
    float* Vs  = Ks  + 64*PAD;
    float* Ss  = Vs  + 64*PAD;
    float* KVs = Ss  + 64*PAD;
    float* Wps = KVs + 64*PAD;
    float* den = Wps + 64*PAD;
    float* kps = den + 64;

    const int t = threadIdx.x;
    const int chunk = blockIdx.x, bh = blockIdx.y;
    const size_t base   = ((size_t)bh * SEQ + chunk * CH) * 64;
    const size_t kvbase = ((size_t)bh * NCHUNK + chunk) * 4096;

    for (int i = t; i < 1024; i += 256) {
        int r = i >> 4, c4 = (i & 15) << 2;
        *(float4*)&Qs [r*PAD + c4] = *(const float4*)(phiQ + base   + (size_t)r*64 + c4);
        *(float4*)&Ks [r*PAD + c4] = *(const float4*)(phiK + base   + (size_t)r*64 + c4);
        *(float4*)&Vs [r*PAD + c4] = *(const float4*)(Vg   + base   + (size_t)r*64 + c4);
        *(float4*)&KVs[r*PAD + c4] = *(const float4*)(KVp  + kvbase + (size_t)r*64 + c4);
    }
    for (int i = t; i < 4096; i += 256) {
        int e = i >> 6, c = i & 63;
        Wps[c*PAD + e] = Wpost[i];
    }
    if (t < 64) kps[t] = Kp[((size_t)bh * NCHUNK + chunk) * 64 + t];
    __syncthreads();

    const int r  = t >> 2;
    const int c0 = t & 3;

    float sacc[16];
#pragma unroll
    for (int m = 0; m < 16; m++) sacc[m] = 0.f;
#pragma unroll
    for (int d = 0; d < 64; d += 4) {
        float4 q4 = *(const float4*)&Qs[r*PAD + d];
#pragma unroll
        for (int m = 0; m < 16; m++) {
            int j = c0 + 4*m;
            float4 k4 = *(const float4*)&Ks[j*PAD + d];
            sacc[m] += q4.x*k4.x + q4.y*k4.y + q4.z*k4.z + q4.w*k4.w;
        }
    }
    float rs = 0.f;
#pragma unroll
    for (int m = 0; m < 16; m++) {
        int j = c0 + 4*m;
        float sv = (j <= r) ? sacc[m] : 0.f;
        Ss[r*PAD + j] = sv;
        rs += sv;
    }
    float qk = 0.f;
#pragma unroll
    for (int m = 0; m < 16; m++) {
        int c = c0 + 4*m;
        qk += Qs[r*PAD + c] * kps[c];
    }
    float dp = rs + qk;
    dp += __shfl_xor_sync(0xffffffffu, dp, 1);
    dp += __shfl_xor_sync(0xffffffffu, dp, 2);
    if (c0 == 0) den[r] = fmaxf(dp, 1e-6f);
    __syncthreads();

    float oacc[16];
#pragma unroll
    for (int m = 0; m < 16; m++) oacc[m] = 0.f;
#pragma unroll
    for (int j = 0; j < 64; j += 4) {
        float4 s4 = *(const float4*)&Ss[r*PAD + j];
#pragma unroll
        for (int m = 0; m < 16; m++) {
            int c = c0 + 4*m;
            oacc[m] += s4.x*Vs[(j+0)*PAD + c] + s4.y*Vs[(j+1)*PAD + c]
                     + s4.z*Vs[(j+2)*PAD + c] + s4.w*Vs[(j+3)*PAD + c];
        }
    }
#pragma unroll
    for (int f = 0; f < 64; f += 4) {
        float4 q4 = *(const float4*)&Qs[r*PAD + f];
#pragma unroll
        for (int m = 0; m < 16; m++) {
            int c = c0 + 4*m;
            oacc[m] += q4.x*KVs[(f+0)*PAD + c] + q4.y*KVs[(f+1)*PAD + c]
                     + q4.z*KVs[(f+2)*PAD + c] + q4.w*KVs[(f+3)*PAD + c];
        }
    }
    const float inv = 1.0f / den[r];
#pragma unroll
    for (int m = 0; m < 16; m++) oacc[m] *= inv;
    __syncthreads();
#pragma unroll
    for (int m = 0; m < 16; m++) Ss[r*PAD + c0 + 4*m] = oacc[m];
    __syncthreads();

    float facc[16];
#pragma unroll
    for (int m = 0; m < 16; m++) facc[m] = 0.f;
#pragma unroll
    for (int c = 0; c < 64; c += 4) {
        float4 o4 = *(const float4*)&Ss[r*PAD + c];
#pragma unroll
        for (int m = 0; m < 16; m++) {
            int e = c0 + 4*m;
            facc[m] += o4.x*Wps[(c+0)*PAD + e] + o4.y*Wps[(c+1)*PAD + e]
                     + o4.z*Wps[(c+2)*PAD + e] + o4.w*Wps[(c+3)*PAD + e];
        }
    }
    const int bi = bh >> 4, hi = bh & 15;
    const int si = chunk * CH + r;
    float* dst = attn + ((size_t)bi * SEQ + si) * DIM + hi * 64;
#pragma unroll
    for (int m = 0; m < 16; m++) dst[c0 + 4*m] = facc[m];
}

// ================= launch =================
extern "C" void kernel_launch(void* const* d_in, const int* in_sizes, int n_in,
                              void* d_out, int out_size)
{
    const float* x     = (const float*)d_in[0];
    const float* Wq    = (const float*)d_in[1];
    const float* Wk    = (const float*)d_in[2];
    const float* Wv    = (const float*)d_in[3];
    const float* proj  = (const float*)d_in[4];
    const float* Wpost = (const float*)d_in[5];
    const float* Wout  = (const float*)d_in[6];
    float* out = (float*)d_out;

    float *pQ, *pK, *pV, *pphiq, *pphik, *pattn, *pkv, *pks;
    __nv_bfloat16 *pxhi, *pxlo, *pahi, *palo, *pwhi, *pwlo;
    cudaGetSymbolAddress((void**)&pQ, g_Q);
    cudaGetSymbolAddress((void**)&pK, g_K);
    cudaGetSymbolAddress((void**)&pV, g_V);
    cudaGetSymbolAddress((void**)&pphiq, g_phiq);
    cudaGetSymbolAddress((void**)&pphik, g_phik);
    cudaGetSymbolAddress((void**)&pattn, g_attn);
    cudaGetSymbolAddress((void**)&pkv, g_kv);
    cudaGetSymbolAddress((void**)&pks, g_ks);
    cudaGetSymbolAddress((void**)&pxhi, g_xhi);
    cudaGetSymbolAddress((void**)&pxlo, g_xlo);
    cudaGetSymbolAddress((void**)&pahi, g_ahi);
    cudaGetSymbolAddress((void**)&palo, g_alo);
    cudaGetSymbolAddress((void**)&pwhi, g_whi);
    cudaGetSymbolAddress((void**)&pwlo, g_wlo);

    static const size_t chunk_smem = (size_t)(6*64*PAD + 128) * sizeof(float);
    cudaFuncSetAttribute(chunk_out_kernel, cudaFuncAttributeMaxDynamicSharedMemorySize,
                         (int)chunk_smem);
    static const int gemm_smem = 2 * BUFB;      // 81920 B
    cudaFuncSetAttribute(gemm_hmma_split, cudaFuncAttributeMaxDynamicSharedMemorySize, gemm_smem);

    // split conversions
    const int NX4 = (MROWS * DIM) / 4;
    const int NW4 = (DIM * DIM) / 4;
    convert_split<<<NX4/256, 256>>>(x,    pxhi, pxlo, NX4);
    convert_split<<<NW4/256, 256>>>(Wq,   pwhi + 0*DIM*DIM, pwlo + 0*DIM*DIM, NW4);
    convert_split<<<NW4/256, 256>>>(Wk,   pwhi + 1*DIM*DIM, pwlo + 1*DIM*DIM, NW4);
    convert_split<<<NW4/256, 256>>>(Wv,   pwhi + 2*DIM*DIM, pwlo + 2*DIM*DIM, NW4);
    convert_split<<<NW4/256, 256>>>(Wout, pwhi + 3*DIM*DIM, pwlo + 3*DIM*DIM, NW4);

    dim3 gg(DIM/128, MROWS/128);     // (8, 64)
    gemm_hmma_split<<<gg, 256, gemm_smem>>>(pxhi, pxlo, pwhi + 0*DIM*DIM, pwlo + 0*DIM*DIM, pQ, MROWS, DIM, DIM);
    gemm_hmma_split<<<gg, 256, gemm_smem>>>(pxhi, pxlo, pwhi + 1*DIM*DIM, pwlo + 1*DIM*DIM, pK, MROWS, DIM, DIM);
    gemm_hmma_split<<<gg, 256, gemm_smem>>>(pxhi, pxlo, pwhi + 2*DIM*DIM, pwlo + 2*DIM*DIM, pV, MROWS, DIM, DIM);

    feature_kernel<<<ROWS/64, 256>>>(pQ, proj, pphiq, 1);
    feature_kernel<<<ROWS/64, 256>>>(pK, proj, pphik, 0);

    dim3 gc(NCHUNK, NBH);            // (32, 64)
    chunk_local_kernel<<<gc, 256>>>(pphik, pV, pkv, pks);
    prefix_kernel<<<NBH, 256>>>(pkv, pks);
    chunk_out_kernel<<<gc, 256, chunk_smem>>>(pphiq, pphik, pV, pkv, pks, Wpost, pattn);

    convert_split<<<NX4/256, 256>>>(pattn, pahi, palo, NX4);
    gemm_hmma_split<<<gg, 256, gemm_smem>>>(pahi, palo, pwhi + 3*DIM*DIM, pwlo + 3*DIM*DIM, out, MROWS, DIM, DIM);
}

// round 5
// speedup vs baseline: 2.5843x; 1.1467x over previous
#include <cuda_runtime.h>
#include <cuda_bf16.h>
#include <math.h>
#include <cstdint>

// Problem constants
#define BATCH 4
#define SEQ   2048
#define DIM   1024
#define HEADS 16
#define DH    64
#define NF    64
#define NBH   (BATCH*HEADS)          // 64
#define ROWS  (NBH*SEQ)              // 131072 head-rows
#define MROWS (BATCH*SEQ)            // 8192 GEMM rows
#define CH    64                     // chunk length
#define NCHUNK (SEQ/CH)              // 32
#define PAD   68

// ---------------- device scratch ----------------
__device__ float g_Q[ROWS*DH];
__device__ float g_K[ROWS*DH];
__device__ float g_V[ROWS*DH];
__device__ float g_phiq[ROWS*NF];
__device__ float g_phik[ROWS*NF];
__device__ float g_kv[NBH*NCHUNK*NF*DH];
__device__ float g_ks[NBH*NCHUNK*NF];
// bf16 split buffers
__device__ __nv_bfloat16 g_xhi[MROWS*DIM];
__device__ __nv_bfloat16 g_xlo[MROWS*DIM];
__device__ __nv_bfloat16 g_ahi[MROWS*DIM];
__device__ __nv_bfloat16 g_alo[MROWS*DIM];
__device__ __nv_bfloat16 g_whi[4*DIM*DIM];
__device__ __nv_bfloat16 g_wlo[4*DIM*DIM];

// ================= helpers =================
__device__ __forceinline__ uint32_t smem_u32(const void* p) {
    uint32_t a;
    asm("{ .reg .u64 tmp; cvta.to.shared.u64 tmp, %1; cvt.u32.u64 %0, tmp; }" : "=r"(a) : "l"(p));
    return a;
}
__device__ __forceinline__ void ldm_x4(uint32_t* r, uint32_t addr) {
    asm volatile("ldmatrix.sync.aligned.m8n8.x4.shared.b16 {%0,%1,%2,%3}, [%4];"
        : "=r"(r[0]), "=r"(r[1]), "=r"(r[2]), "=r"(r[3]) : "r"(addr));
}
__device__ __forceinline__ void mma_bf16(float* d, const uint32_t* a, const uint32_t* b) {
    asm volatile("mma.sync.aligned.m16n8k16.row.col.f32.bf16.bf16.f32 "
        "{%0,%1,%2,%3}, {%4,%5,%6,%7}, {%8,%9}, {%0,%1,%2,%3};"
        : "+f"(d[0]), "+f"(d[1]), "+f"(d[2]), "+f"(d[3])
        : "r"(a[0]), "r"(a[1]), "r"(a[2]), "r"(a[3]), "r"(b[0]), "r"(b[1]));
}
__device__ __forceinline__ void cp16(uint32_t dst, const void* src) {
    asm volatile("cp.async.cg.shared.global [%0], [%1], 16;" :: "r"(dst), "l"(src));
}
#define CP_COMMIT() asm volatile("cp.async.commit_group;" ::: "memory")
#define CP_WAIT(N)  asm volatile("cp.async.wait_group %0;" :: "n"(N) : "memory")

// ================= split conversion =================
__global__ __launch_bounds__(256) void convert_split(const float* __restrict__ s,
                                                     __nv_bfloat16* __restrict__ hi,
                                                     __nv_bfloat16* __restrict__ lo, int n4)
{
    int i = blockIdx.x * 256 + threadIdx.x;
    if (i >= n4) return;
    float4 v = ((const float4*)s)[i];
    __nv_bfloat16 h0 = __float2bfloat16(v.x);
    __nv_bfloat16 h1 = __float2bfloat16(v.y);
    __nv_bfloat16 h2 = __float2bfloat16(v.z);
    __nv_bfloat16 h3 = __float2bfloat16(v.w);
    __nv_bfloat16 l0 = __float2bfloat16(v.x - __bfloat162float(h0));
    __nv_bfloat16 l1 = __float2bfloat16(v.y - __bfloat162float(h1));
    __nv_bfloat16 l2 = __float2bfloat16(v.z - __bfloat162float(h2));
    __nv_bfloat16 l3 = __float2bfloat16(v.w - __bfloat162float(h3));
    __nv_bfloat162 p;
    p.x = h0; p.y = h1; ((__nv_bfloat162*)hi)[2*i]   = p;
    p.x = h2; p.y = h3; ((__nv_bfloat162*)hi)[2*i+1] = p;
    p.x = l0; p.y = l1; ((__nv_bfloat162*)lo)[2*i]   = p;
    p.x = l2; p.y = l3; ((__nv_bfloat162*)lo)[2*i+1] = p;
}

// ================= HMMA split-bf16 GEMM (cp.async, 2 CTA/SM) =================
// C[M,N=1024] = A[M,K] @ B[N,K]^T with A=Ahi+Alo, B=Bhi+Blo (drop lo*lo).
// Grid.x = 8*ngroups; group = blockIdx.x>>3 selects weight slice + output buffer.
#define ASTR 40                        // smem row stride in bf16 (80 B, ldmatrix conflict-free)
#define TILE_SMEM (128*ASTR*2)         // 10240 B per 128x32 tile
#define BUFB (4*TILE_SMEM)             // Ahi,Alo,Bhi,Blo per buffer (40960 B)

__global__ __launch_bounds__(256, 2) void gemm_hmma_split(
    const __nv_bfloat16* __restrict__ Ahi, const __nv_bfloat16* __restrict__ Alo,
    const __nv_bfloat16* __restrict__ Bhi_all, const __nv_bfloat16* __restrict__ Blo_all,
    float* __restrict__ C0, float* __restrict__ C1, float* __restrict__ C2, int K)
{
    extern __shared__ char smx[];
    const int t = threadIdx.x;
    const int wid = t >> 5, lane = t & 31;
    const int wm = wid >> 2, wn = wid & 3;
    const int bm = blockIdx.y * 128;
    const int which = blockIdx.x >> 3;
    const int bn = (blockIdx.x & 7) * 128;
    const __nv_bfloat16* Bh = Bhi_all + (size_t)which * DIM * DIM;
    const __nv_bfloat16* Bl = Blo_all + (size_t)which * DIM * DIM;
    float* C = (which == 0) ? C0 : (which == 1) ? C1 : C2;

    const uint32_t smb = smem_u32(smx);
    const __nv_bfloat16* srcs[4] = {Ahi, Alo, Bh, Bl};

    float acc[4][4][4];
#pragma unroll
    for (int i = 0; i < 4; i++)
#pragma unroll
        for (int j = 0; j < 4; j++)
#pragma unroll
            for (int q = 0; q < 4; q++) acc[i][j][q] = 0.f;

    // ---- cp.async one k-slab into buffer b ----
    auto issue = [&](int s, int b) {
        const int k0 = s * 32;
#pragma unroll
        for (int q = 0; q < 8; q++) {
            int tile = q >> 1;
            int i = (q & 1) * 256 + t;          // 0..511
            int r = i >> 2, ch = i & 3;
            int rb = (tile < 2) ? bm : bn;
            cp16(smb + b * BUFB + tile * TILE_SMEM + r * 80 + ch * 16,
                 srcs[tile] + (size_t)(rb + r) * K + k0 + ch * 8);
        }
        CP_COMMIT();
    };

    // ---- compute one k-slab from buffer b ----
    auto compute = [&](int b) {
        const uint32_t Ahb = smb + b * BUFB;
        const uint32_t Alb = Ahb + TILE_SMEM;
        const uint32_t Bhb = Ahb + 2 * TILE_SMEM;
        const uint32_t Blb = Ahb + 3 * TILE_SMEM;
        const int lrA = lane & 15, kbA = lane >> 4;
        const int nrB = (lane & 7) + ((lane >> 4) << 3);
        const int kbB = (lane >> 3) & 1;
#pragma unroll
        for (int ks = 0; ks < 2; ks++) {
            uint32_t bhf[4][2], blf[4][2];
#pragma unroll
            for (int np = 0; np < 2; np++) {
                uint32_t off = (uint32_t)((wn * 32 + np * 16 + nrB) * 80 + ks * 32 + kbB * 16);
                uint32_t tmp[4];
                ldm_x4(tmp, Bhb + off);
                bhf[2*np][0] = tmp[0]; bhf[2*np][1] = tmp[1];
                bhf[2*np+1][0] = tmp[2]; bhf[2*np+1][1] = tmp[3];
                ldm_x4(tmp, Blb + off);
                blf[2*np][0] = tmp[0]; blf[2*np][1] = tmp[1];
                blf[2*np+1][0] = tmp[2]; blf[2*np+1][1] = tmp[3];
            }
#pragma unroll
            for (int ma = 0; ma < 4; ma++) {
                uint32_t ah[4], al[4];
                uint32_t off = (uint32_t)((wm * 64 + ma * 16 + lrA) * 80 + ks * 32 + kbA * 16);
                ldm_x4(ah, Ahb + off);
                ldm_x4(al, Alb + off);
#pragma unroll
                for (int na = 0; na < 4; na++) {
                    mma_bf16(acc[ma][na], ah, bhf[na]);
                    mma_bf16(acc[ma][na], ah, blf[na]);
                    mma_bf16(acc[ma][na], al, bhf[na]);
                }
            }
        }
    };

    const int S = K / 32;
    issue(0, 0);
    for (int s = 0; s < S; s++) {
        if (s + 1 < S) { issue(s + 1, (s + 1) & 1); CP_WAIT(1); }
        else           { CP_WAIT(0); }
        __syncthreads();
        compute(s & 1);
        __syncthreads();
    }

    // ---- epilogue ----
    const int g = lane >> 2, tig = lane & 3;
#pragma unroll
    for (int ma = 0; ma < 4; ma++) {
        const int r0 = bm + wm * 64 + ma * 16 + g;
#pragma unroll
        for (int na = 0; na < 4; na++) {
            const int c = bn + wn * 32 + na * 8 + tig * 2;
            *(float2*)(C + (size_t)r0 * DIM + c)       = make_float2(acc[ma][na][0], acc[ma][na][1]);
            *(float2*)(C + (size_t)(r0 + 8) * DIM + c) = make_float2(acc[ma][na][2], acc[ma][na][3]);
        }
    }
}

// ================= feature map (register-tiled 64x64 mini-GEMM) =================
__global__ __launch_bounds__(256) void feature_kernel(const float* __restrict__ X,
                                                      const float* __restrict__ proj,
                                                      float* __restrict__ phi,
                                                      int is_query)
{
    __shared__ float XsT[64*PAD];   // [d][r]
    __shared__ float pT[64*PAD];    // [d][f]
    const int t = threadIdx.x;
    const size_t base = (size_t)blockIdx.x * 64 * 64;

    for (int i = t; i < 4096; i += 256) { int f_ = i >> 6, d_ = i & 63; pT[d_*PAD + f_] = proj[i]; }
    for (int i = t; i < 4096; i += 256) { int r_ = i >> 6, d_ = i & 63; XsT[d_*PAD + r_] = X[base + i]; }
    __syncthreads();

    const int r0 = (t >> 4) << 2;
    const int f0 = (t & 15) << 2;
    float acc[4][4], sq[4];
#pragma unroll
    for (int i = 0; i < 4; i++) { sq[i] = 0.f;
#pragma unroll
        for (int j = 0; j < 4; j++) acc[i][j] = 0.f; }

#pragma unroll
    for (int d = 0; d < 64; d++) {
        float4 a = *(const float4*)&XsT[d*PAD + r0];
        float4 b = *(const float4*)&pT[d*PAD + f0];
        float av[4] = {a.x, a.y, a.z, a.w};
        float bv[4] = {b.x, b.y, b.z, b.w};
#pragma unroll
        for (int i = 0; i < 4; i++) {
            sq[i] += av[i] * av[i];
#pragma unroll
            for (int j = 0; j < 4; j++) acc[i][j] += av[i] * bv[j];
        }
    }
    const float dn = 0.35355339059327373f;   // 64^{-1/4}
    float dd[4][4];
#pragma unroll
    for (int i = 0; i < 4; i++)
#pragma unroll
        for (int j = 0; j < 4; j++) dd[i][j] = dn * acc[i][j];

    if (is_query) {
#pragma unroll
        for (int i = 0; i < 4; i++) {
            float mx = fmaxf(fmaxf(dd[i][0], dd[i][1]), fmaxf(dd[i][2], dd[i][3]));
#pragma unroll
            for (int o = 8; o >= 1; o >>= 1) mx = fmaxf(mx, __shfl_xor_sync(0xffffffffu, mx, o));
#pragma unroll
            for (int j = 0; j < 4; j++) dd[i][j] -= mx;
        }
    }
#pragma unroll
    for (int i = 0; i < 4; i++) {
        const float diag = sq[i] * (1.0f / 128.0f);
        float4 o;
        o.x = 0.125f * (expf(dd[i][0] - diag) + 1e-4f);
        o.y = 0.125f * (expf(dd[i][1] - diag) + 1e-4f);
        o.z = 0.125f * (expf(dd[i][2] - diag) + 1e-4f);
        o.w = 0.125f * (expf(dd[i][3] - diag) + 1e-4f);
        *(float4*)&phi[((size_t)blockIdx.x * 64 + r0 + i) * 64 + f0] = o;
    }
}

// ================= chunk kernels =================
__global__ __launch_bounds__(256) void chunk_local_kernel(const float* __restrict__ phiK,
                                                          const float* __restrict__ V,
                                                          float* __restrict__ kvloc,
                                                          float* __restrict__ kloc)
{
    __shared__ float ks[16*64];
    __shared__ float vs[16*64];
    const int t = threadIdx.x;
    const int chunk = blockIdx.x, bh = blockIdx.y;
    const size_t base = ((size_t)bh * SEQ + chunk * CH) * 64;
    const int f = t >> 2, c0 = t & 3;

    float acc[16];
#pragma unroll
    for (int m = 0; m < 16; m++) acc[m] = 0.f;
    float kl = 0.f;

    for (int st = 0; st < 4; st++) {
        __syncthreads();
        {
            int r = t >> 4, c4 = (t & 15) << 2;
            *(float4*)&ks[r*64 + c4] = *(const float4*)(phiK + base + (size_t)(st*16 + r)*64 + c4);
            *(float4*)&vs[r*64 + c4] = *(const float4*)(V    + base + (size_t)(st*16 + r)*64 + c4);
        }
        __syncthreads();
#pragma unroll
        for (int r = 0; r < 16; r++) {
            float kv = ks[r*64 + f];
#pragma unroll
            for (int m = 0; m < 16; m++) acc[m] += kv * vs[r*64 + c0 + 4*m];
        }
        if (t < 64) {
#pragma unroll
            for (int r = 0; r < 16; r++) kl += ks[r*64 + t];
        }
    }
    const size_t ob = ((size_t)bh * NCHUNK + chunk) * (64*64);
#pragma unroll
    for (int m = 0; m < 16; m++) kvloc[ob + (size_t)f*64 + c0 + 4*m] = acc[m];
    if (t < 64) kloc[((size_t)bh * NCHUNK + chunk) * 64 + t] = kl;
}

__global__ __launch_bounds__(256) void prefix_kernel(float* __restrict__ kvloc,
                                                     float* __restrict__ kloc)
{
    const int bh = blockIdx.x;
    const int t = threadIdx.x;
    float run[16];
#pragma unroll
    for (int m = 0; m < 16; m++) run[m] = 0.f;
    for (int c = 0; c < NCHUNK; c++) {
        const size_t b = ((size_t)bh * NCHUNK + c) * 4096;
#pragma unroll
        for (int m = 0; m < 16; m++) {
            float v = kvloc[b + t + 256*m];
            kvloc[b + t + 256*m] = run[m];
            run[m] += v;
        }
    }
    if (t < 64) {
        float rk = 0.f;
        for (int c = 0; c < NCHUNK; c++) {
            const size_t b = ((size_t)bh * NCHUNK + c) * 64 + t;
            float v = kloc[b];
            kloc[b] = rk;
            rk += v;
        }
    }
}

// chunk output + Wpost + head-transpose + bf16-split store (feeds final GEMM directly)
__global__ __launch_bounds__(256) void chunk_out_kernel(const float* __restrict__ phiQ,
                                                        const float* __restrict__ phiK,
                                                        const float* __restrict__ Vg,
                                                        const float* __restrict__ KVp,
                                                        const float* __restrict__ Kp,
                                                        const float* __restrict__ Wpost,
                                                        __nv_bfloat16* __restrict__ ahi,
                                                        __nv_bfloat16* __restrict__ alo)
{
    extern __shared__ float sm[];
    float* Qs  = sm;
    float* Ks  = Qs  + 64*PAD;
    float* Vs  = Ks  + 64*PAD;
    float* Ss  = Vs  + 64*PAD;
    float* KVs = Ss  + 64*PAD;
    float* Wps = KVs + 64*PAD;
    float* den = Wps + 64*PAD;
    float* kps = den + 64;

    const int t = threadIdx.x;
    const int chunk = blockIdx.x, bh = blockIdx.y;
    const size_t base   = ((size_t)bh * SEQ + chunk * CH) * 64;
    const size_t kvbase = ((size_t)bh * NCHUNK + chunk) * 4096;

    for (int i = t; i < 1024; i += 256) {
        int r = i >> 4, c4 = (i & 15) << 2;
        *(float4*)&Qs [r*PAD + c4] = *(const float4*)(phiQ + base   + (size_t)r*64 + c4);
        *(float4*)&Ks [r*PAD + c4] = *(const float4*)(phiK + base   + (size_t)r*64 + c4);
        *(float4*)&Vs [r*PAD + c4] = *(const float4*)(Vg   + base   + (size_t)r*64 + c4);
        *(float4*)&KVs[r*PAD + c4] = *(const float4*)(KVp  + kvbase + (size_t)r*64 + c4);
    }
    for (int i = t; i < 4096; i += 256) {
        int e = i >> 6, c = i & 63;
        Wps[c*PAD + e] = Wpost[i];
    }
    if (t < 64) kps[t] = Kp[((size_t)bh * NCHUNK + chunk) * 64 + t];
    __syncthreads();

    const int r  = t >> 2;
    const int c0 = t & 3;

    float sacc[16];
#pragma unroll
    for (int m = 0; m < 16; m++) sacc[m] = 0.f;
#pragma unroll
    for (int d = 0; d < 64; d += 4) {
        float4 q4 = *(const float4*)&Qs[r*PAD + d];
#pragma unroll
        for (int m = 0; m < 16; m++) {
            int j = c0 + 4*m;
            float4 k4 = *(const float4*)&Ks[j*PAD + d];
            sacc[m] += q4.x*k4.x + q4.y*k4.y + q4.z*k4.z + q4.w*k4.w;
        }
    }
    float rs = 0.f;
#pragma unroll
    for (int m = 0; m < 16; m++) {
        int j = c0 + 4*m;
        float sv = (j <= r) ? sacc[m] : 0.f;
        Ss[r*PAD + j] = sv;
        rs += sv;
    }
    float qk = 0.f;
#pragma unroll
    for (int m = 0; m < 16; m++) {
        int c = c0 + 4*m;
        qk += Qs[r*PAD + c] * kps[c];
    }
    float dp = rs + qk;
    dp += __shfl_xor_sync(0xffffffffu, dp, 1);
    dp += __shfl_xor_sync(0xffffffffu, dp, 2);
    if (c0 == 0) den[r] = fmaxf(dp, 1e-6f);
    __syncthreads();

    float oacc[16];
#pragma unroll
    for (int m = 0; m < 16; m++) oacc[m] = 0.f;
#pragma unroll
    for (int j = 0; j < 64; j += 4) {
        float4 s4 = *(const float4*)&Ss[r*PAD + j];
#pragma unroll
        for (int m = 0; m < 16; m++) {
            int c = c0 + 4*m;
            oacc[m] += s4.x*Vs[(j+0)*PAD + c] + s4.y*Vs[(j+1)*PAD + c]
                     + s4.z*Vs[(j+2)*PAD + c] + s4.w*Vs[(j+3)*PAD + c];
        }
    }
#pragma unroll
    for (int f = 0; f < 64; f += 4) {
        float4 q4 = *(const float4*)&Qs[r*PAD + f];
#pragma unroll
        for (int m = 0; m < 16; m++) {
            int c = c0 + 4*m;
            oacc[m] += q4.x*KVs[(f+0)*PAD + c] + q4.y*KVs[(f+1)*PAD + c]
                     + q4.z*KVs[(f+2)*PAD + c] + q4.w*KVs[(f+3)*PAD + c];
        }
    }
    const float inv = 1.0f / den[r];
#pragma unroll
    for (int m = 0; m < 16; m++) oacc[m] *= inv;
    __syncthreads();
#pragma unroll
    for (int m = 0; m < 16; m++) Ss[r*PAD + c0 + 4*m] = oacc[m];
    __syncthreads();

    float facc[16];
#pragma unroll
    for (int m = 0; m < 16; m++) facc[m] = 0.f;
#pragma unroll
    for (int c = 0; c < 64; c += 4) {
        float4 o4 = *(const float4*)&Ss[r*PAD + c];
#pragma unroll
        for (int m = 0; m < 16; m++) {
            int e = c0 + 4*m;
            facc[m] += o4.x*Wps[(c+0)*PAD + e] + o4.y*Wps[(c+1)*PAD + e]
                     + o4.z*Wps[(c+2)*PAD + e] + o4.w*Wps[(c+3)*PAD + e];
        }
    }
    const int bi = bh >> 4, hi2 = bh & 15;
    const int si = chunk * CH + r;
    const size_t ob = ((size_t)bi * SEQ + si) * DIM + hi2 * 64;
#pragma unroll
    for (int m = 0; m < 16; m++) {
        float f = facc[m];
        __nv_bfloat16 h = __float2bfloat16(f);
        ahi[ob + c0 + 4*m] = h;
        alo[ob + c0 + 4*m] = __float2bfloat16(f - __bfloat162float(h));
    }
}

// ================= launch =================
extern "C" void kernel_launch(void* const* d_in, const int* in_sizes, int n_in,
                              void* d_out, int out_size)
{
    const float* x     = (const float*)d_in[0];
    const float* Wq    = (const float*)d_in[1];
    const float* Wk    = (const float*)d_in[2];
    const float* Wv    = (const float*)d_in[3];
    const float* proj  = (const float*)d_in[4];
    const float* Wpost = (const float*)d_in[5];
    const float* Wout  = (const float*)d_in[6];
    float* out = (float*)d_out;

    float *pQ, *pK, *pV, *pphiq, *pphik, *pkv, *pks;
    __nv_bfloat16 *pxhi, *pxlo, *pahi, *palo, *pwhi, *pwlo;
    cudaGetSymbolAddress((void**)&pQ, g_Q);
    cudaGetSymbolAddress((void**)&pK, g_K);
    cudaGetSymbolAddress((void**)&pV, g_V);
    cudaGetSymbolAddress((void**)&pphiq, g_phiq);
    cudaGetSymbolAddress((void**)&pphik, g_phik);
    cudaGetSymbolAddress((void**)&pkv, g_kv);
    cudaGetSymbolAddress((void**)&pks, g_ks);
    cudaGetSymbolAddress((void**)&pxhi, g_xhi);
    cudaGetSymbolAddress((void**)&pxlo, g_xlo);
    cudaGetSymbolAddress((void**)&pahi, g_ahi);
    cudaGetSymbolAddress((void**)&palo, g_alo);
    cudaGetSymbolAddress((void**)&pwhi, g_whi);
    cudaGetSymbolAddress((void**)&pwlo, g_wlo);

    static const size_t chunk_smem = (size_t)(6*64*PAD + 128) * sizeof(float);
    cudaFuncSetAttribute(chunk_out_kernel, cudaFuncAttributeMaxDynamicSharedMemorySize,
                         (int)chunk_smem);
    static const int gemm_smem = 2 * BUFB;      // 81920 B
    cudaFuncSetAttribute(gemm_hmma_split, cudaFuncAttributeMaxDynamicSharedMemorySize, gemm_smem);

    // split conversions
    const int NX4 = (MROWS * DIM) / 4;
    const int NW4 = (DIM * DIM) / 4;
    convert_split<<<NX4/256, 256>>>(x,    pxhi, pxlo, NX4);
    convert_split<<<NW4/256, 256>>>(Wq,   pwhi + 0*DIM*DIM, pwlo + 0*DIM*DIM, NW4);
    convert_split<<<NW4/256, 256>>>(Wk,   pwhi + 1*DIM*DIM, pwlo + 1*DIM*DIM, NW4);
    convert_split<<<NW4/256, 256>>>(Wv,   pwhi + 2*DIM*DIM, pwlo + 2*DIM*DIM, NW4);
    convert_split<<<NW4/256, 256>>>(Wout, pwhi + 3*DIM*DIM, pwlo + 3*DIM*DIM, NW4);

    // fused Q/K/V projection: grid.x covers 3 weight groups of 8 column-tiles
    dim3 gqkv(24, MROWS/128);
    gemm_hmma_split<<<gqkv, 256, gemm_smem>>>(pxhi, pxlo, pwhi, pwlo, pQ, pK, pV, DIM);

    feature_kernel<<<ROWS/64, 256>>>(pQ, proj, pphiq, 1);
    feature_kernel<<<ROWS/64, 256>>>(pK, proj, pphik, 0);

    dim3 gc(NCHUNK, NBH);            // (32, 64)
    chunk_local_kernel<<<gc, 256>>>(pphik, pV, pkv, pks);
    prefix_kernel<<<NBH, 256>>>(pkv, pks);
    chunk_out_kernel<<<gc, 256, chunk_smem>>>(pphiq, pphik, pV, pkv, pks, Wpost, pahi, palo);

    // final output projection
    dim3 gout(8, MROWS/128);
    gemm_hmma_split<<<gout, 256, gemm_smem>>>(pahi, palo, pwhi + 3*DIM*DIM, pwlo + 3*DIM*DIM,
                                              out, out, out, DIM);
}

// round 6
// speedup vs baseline: 2.6213x; 1.0143x over previous
#include <cuda_runtime.h>
#include <cuda_bf16.h>
#include <math.h>
#include <cstdint>

// Problem constants
#define BATCH 4
#define SEQ   2048
#define DIM   1024
#define HEADS 16
#define DH    64
#define NF    64
#define NBH   (BATCH*HEADS)          // 64
#define ROWS  (NBH*SEQ)              // 131072 head-rows
#define MROWS (BATCH*SEQ)            // 8192 GEMM rows
#define CH    64                     // chunk length
#define NCHUNK (SEQ/CH)              // 32
#define PAD   68

// ---------------- device scratch ----------------
__device__ float g_Q[ROWS*DH];
__device__ float g_K[ROWS*DH];
__device__ float g_V[ROWS*DH];
__device__ float g_phiq[ROWS*NF];
__device__ float g_phik[ROWS*NF];
__device__ float g_kv[NBH*NCHUNK*NF*DH];
__device__ float g_ks[NBH*NCHUNK*NF];
// bf16 split buffers
__device__ __nv_bfloat16 g_xhi[MROWS*DIM];
__device__ __nv_bfloat16 g_xlo[MROWS*DIM];
__device__ __nv_bfloat16 g_ahi[MROWS*DIM];
__device__ __nv_bfloat16 g_alo[MROWS*DIM];
__device__ __nv_bfloat16 g_whi[4*DIM*DIM];
__device__ __nv_bfloat16 g_wlo[4*DIM*DIM];

// ================= helpers =================
__device__ __forceinline__ uint32_t smem_u32(const void* p) {
    uint32_t a;
    asm("{ .reg .u64 tmp; cvta.to.shared.u64 tmp, %1; cvt.u32.u64 %0, tmp; }" : "=r"(a) : "l"(p));
    return a;
}
__device__ __forceinline__ void ldm_x4(uint32_t* r, uint32_t addr) {
    asm volatile("ldmatrix.sync.aligned.m8n8.x4.shared.b16 {%0,%1,%2,%3}, [%4];"
        : "=r"(r[0]), "=r"(r[1]), "=r"(r[2]), "=r"(r[3]) : "r"(addr));
}
__device__ __forceinline__ void mma_bf16(float* d, const uint32_t* a, const uint32_t* b) {
    asm volatile("mma.sync.aligned.m16n8k16.row.col.f32.bf16.bf16.f32 "
        "{%0,%1,%2,%3}, {%4,%5,%6,%7}, {%8,%9}, {%0,%1,%2,%3};"
        : "+f"(d[0]), "+f"(d[1]), "+f"(d[2]), "+f"(d[3])
        : "r"(a[0]), "r"(a[1]), "r"(a[2]), "r"(a[3]), "r"(b[0]), "r"(b[1]));
}
__device__ __forceinline__ void cp16(uint32_t dst, const void* src) {
    asm volatile("cp.async.cg.shared.global [%0], [%1], 16;" :: "r"(dst), "l"(src));
}
#define CP_COMMIT() asm volatile("cp.async.commit_group;" ::: "memory")
#define CP_WAIT(N)  asm volatile("cp.async.wait_group %0;" :: "n"(N) : "memory")

// ================= fused split conversion (x + 4 weights, one launch) =================
// blocks [0, 8192): x -> xhi/xlo ; blocks [8192, 12288): weight w -> whi/wlo slice
__global__ __launch_bounds__(256) void convert_all(
    const float* __restrict__ x,
    const float* __restrict__ Wq, const float* __restrict__ Wk,
    const float* __restrict__ Wv, const float* __restrict__ Wout,
    __nv_bfloat16* __restrict__ xhi, __nv_bfloat16* __restrict__ xlo,
    __nv_bfloat16* __restrict__ whi, __nv_bfloat16* __restrict__ wlo)
{
    const int b = blockIdx.x;
    const float* src;
    __nv_bfloat16 *hi, *lo;
    int i;
    if (b < 8192) {
        src = x; hi = xhi; lo = xlo;
        i = b * 256 + threadIdx.x;
    } else {
        const int wb = b - 8192;
        const int w = wb >> 10;          // 1024 blocks per weight
        const int r = wb & 1023;
        src = (w == 0) ? Wq : (w == 1) ? Wk : (w == 2) ? Wv : Wout;
        hi = whi + (size_t)w * DIM * DIM;
        lo = wlo + (size_t)w * DIM * DIM;
        i = r * 256 + threadIdx.x;
    }
    float4 v = ((const float4*)src)[i];
    __nv_bfloat16 h0 = __float2bfloat16(v.x);
    __nv_bfloat16 h1 = __float2bfloat16(v.y);
    __nv_bfloat16 h2 = __float2bfloat16(v.z);
    __nv_bfloat16 h3 = __float2bfloat16(v.w);
    __nv_bfloat16 l0 = __float2bfloat16(v.x - __bfloat162float(h0));
    __nv_bfloat16 l1 = __float2bfloat16(v.y - __bfloat162float(h1));
    __nv_bfloat16 l2 = __float2bfloat16(v.z - __bfloat162float(h2));
    __nv_bfloat16 l3 = __float2bfloat16(v.w - __bfloat162float(h3));
    __nv_bfloat162 p;
    p.x = h0; p.y = h1; ((__nv_bfloat162*)hi)[2*i]   = p;
    p.x = h2; p.y = h3; ((__nv_bfloat162*)hi)[2*i+1] = p;
    p.x = l0; p.y = l1; ((__nv_bfloat162*)lo)[2*i]   = p;
    p.x = l2; p.y = l3; ((__nv_bfloat162*)lo)[2*i+1] = p;
}

// ================= HMMA split-bf16 GEMM (cp.async, 2 CTA/SM, 1 sync/slab) =================
#define ASTR 40                        // smem row stride in bf16 (80 B, ldmatrix conflict-free)
#define TILE_SMEM (128*ASTR*2)         // 10240 B per 128x32 tile
#define BUFB (4*TILE_SMEM)             // Ahi,Alo,Bhi,Blo per buffer (40960 B)

__global__ __launch_bounds__(256, 2) void gemm_hmma_split(
    const __nv_bfloat16* __restrict__ Ahi, const __nv_bfloat16* __restrict__ Alo,
    const __nv_bfloat16* __restrict__ Bhi_all, const __nv_bfloat16* __restrict__ Blo_all,
    float* __restrict__ C0, float* __restrict__ C1, float* __restrict__ C2, int K)
{
    extern __shared__ char smx[];
    const int t = threadIdx.x;
    const int wid = t >> 5, lane = t & 31;
    const int wm = wid >> 2, wn = wid & 3;
    const int bm = blockIdx.y * 128;
    const int which = blockIdx.x >> 3;
    const int bn = (blockIdx.x & 7) * 128;
    const __nv_bfloat16* Bh = Bhi_all + (size_t)which * DIM * DIM;
    const __nv_bfloat16* Bl = Blo_all + (size_t)which * DIM * DIM;
    float* C = (which == 0) ? C0 : (which == 1) ? C1 : C2;

    const uint32_t smb = smem_u32(smx);
    const __nv_bfloat16* srcs[4] = {Ahi, Alo, Bh, Bl};

    float acc[4][4][4];
#pragma unroll
    for (int i = 0; i < 4; i++)
#pragma unroll
        for (int j = 0; j < 4; j++)
#pragma unroll
            for (int q = 0; q < 4; q++) acc[i][j][q] = 0.f;

    // ---- cp.async one k-slab into buffer b ----
    auto issue = [&](int s, int b) {
        const int k0 = s * 32;
#pragma unroll
        for (int q = 0; q < 8; q++) {
            int tile = q >> 1;
            int i = (q & 1) * 256 + t;          // 0..511
            int r = i >> 2, ch = i & 3;
            int rb = (tile < 2) ? bm : bn;
            cp16(smb + b * BUFB + tile * TILE_SMEM + r * 80 + ch * 16,
                 srcs[tile] + (size_t)(rb + r) * K + k0 + ch * 8);
        }
        CP_COMMIT();
    };

    // ---- compute one k-slab from buffer b ----
    auto compute = [&](int b) {
        const uint32_t Ahb = smb + b * BUFB;
        const uint32_t Alb = Ahb + TILE_SMEM;
        const uint32_t Bhb = Ahb + 2 * TILE_SMEM;
        const uint32_t Blb = Ahb + 3 * TILE_SMEM;
        const int lrA = lane & 15, kbA = lane >> 4;
        const int nrB = (lane & 7) + ((lane >> 4) << 3);
        const int kbB = (lane >> 3) & 1;
#pragma unroll
        for (int ks = 0; ks < 2; ks++) {
            uint32_t bhf[4][2], blf[4][2];
#pragma unroll
            for (int np = 0; np < 2; np++) {
                uint32_t off = (uint32_t)((wn * 32 + np * 16 + nrB) * 80 + ks * 32 + kbB * 16);
                uint32_t tmp[4];
                ldm_x4(tmp, Bhb + off);
                bhf[2*np][0] = tmp[0]; bhf[2*np][1] = tmp[1];
                bhf[2*np+1][0] = tmp[2]; bhf[2*np+1][1] = tmp[3];
                ldm_x4(tmp, Blb + off);
                blf[2*np][0] = tmp[0]; blf[2*np][1] = tmp[1];
                blf[2*np+1][0] = tmp[2]; blf[2*np+1][1] = tmp[3];
            }
#pragma unroll
            for (int ma = 0; ma < 4; ma++) {
                uint32_t ah[4], al[4];
                uint32_t off = (uint32_t)((wm * 64 + ma * 16 + lrA) * 80 + ks * 32 + kbA * 16);
                ldm_x4(ah, Ahb + off);
                ldm_x4(al, Alb + off);
#pragma unroll
                for (int na = 0; na < 4; na++) {
                    mma_bf16(acc[ma][na], ah, bhf[na]);
                    mma_bf16(acc[ma][na], ah, blf[na]);
                    mma_bf16(acc[ma][na], al, bhf[na]);
                }
            }
        }
    };

    const int S = K / 32;
    issue(0, 0);
    // single __syncthreads per slab; loads of slab s+1 overlap compute(s)
    for (int s = 0; s < S; s++) {
        CP_WAIT(0);
        __syncthreads();
        if (s + 1 < S) issue(s + 1, (s + 1) & 1);
        compute(s & 1);
    }

    // ---- epilogue ----
    const int g = lane >> 2, tig = lane & 3;
#pragma unroll
    for (int ma = 0; ma < 4; ma++) {
        const int r0 = bm + wm * 64 + ma * 16 + g;
#pragma unroll
        for (int na = 0; na < 4; na++) {
            const int c = bn + wn * 32 + na * 8 + tig * 2;
            *(float2*)(C + (size_t)r0 * DIM + c)       = make_float2(acc[ma][na][0], acc[ma][na][1]);
            *(float2*)(C + (size_t)(r0 + 8) * DIM + c) = make_float2(acc[ma][na][2], acc[ma][na][3]);
        }
    }
}

// ================= fused feature map (Q and K in one launch) =================
__global__ __launch_bounds__(256) void feature_both(const float* __restrict__ Q,
                                                    const float* __restrict__ Kd,
                                                    const float* __restrict__ proj,
                                                    float* __restrict__ phiq,
                                                    float* __restrict__ phik)
{
    __shared__ float XsT[64*PAD];   // [d][r]
    __shared__ float pT[64*PAD];    // [d][f]
    const int t = threadIdx.x;
    const int nb = ROWS / 64;       // 2048 blocks per path
    const int is_query = (blockIdx.x < nb) ? 1 : 0;
    const int blk = is_query ? blockIdx.x : blockIdx.x - nb;
    const float* X = is_query ? Q : Kd;
    float* phi = is_query ? phiq : phik;
    const size_t base = (size_t)blk * 64 * 64;

    for (int i = t; i < 4096; i += 256) { int f_ = i >> 6, d_ = i & 63; pT[d_*PAD + f_] = proj[i]; }
    for (int i = t; i < 4096; i += 256) { int r_ = i >> 6, d_ = i & 63; XsT[d_*PAD + r_] = X[base + i]; }
    __syncthreads();

    const int r0 = (t >> 4) << 2;
    const int f0 = (t & 15) << 2;
    float acc[4][4], sq[4];
#pragma unroll
    for (int i = 0; i < 4; i++) { sq[i] = 0.f;
#pragma unroll
        for (int j = 0; j < 4; j++) acc[i][j] = 0.f; }

#pragma unroll
    for (int d = 0; d < 64; d++) {
        float4 a = *(const float4*)&XsT[d*PAD + r0];
        float4 b = *(const float4*)&pT[d*PAD + f0];
        float av[4] = {a.x, a.y, a.z, a.w};
        float bv[4] = {b.x, b.y, b.z, b.w};
#pragma unroll
        for (int i = 0; i < 4; i++) {
            sq[i] += av[i] * av[i];
#pragma unroll
            for (int j = 0; j < 4; j++) acc[i][j] += av[i] * bv[j];
        }
    }
    const float dn = 0.35355339059327373f;   // 64^{-1/4}
    float dd[4][4];
#pragma unroll
    for (int i = 0; i < 4; i++)
#pragma unroll
        for (int j = 0; j < 4; j++) dd[i][j] = dn * acc[i][j];

    if (is_query) {
#pragma unroll
        for (int i = 0; i < 4; i++) {
            float mx = fmaxf(fmaxf(dd[i][0], dd[i][1]), fmaxf(dd[i][2], dd[i][3]));
#pragma unroll
            for (int o = 8; o >= 1; o >>= 1) mx = fmaxf(mx, __shfl_xor_sync(0xffffffffu, mx, o));
#pragma unroll
            for (int j = 0; j < 4; j++) dd[i][j] -= mx;
        }
    }
#pragma unroll
    for (int i = 0; i < 4; i++) {
        const float diag = sq[i] * (1.0f / 128.0f);
        float4 o;
        o.x = 0.125f * (expf(dd[i][0] - diag) + 1e-4f);
        o.y = 0.125f * (expf(dd[i][1] - diag) + 1e-4f);
        o.z = 0.125f * (expf(dd[i][2] - diag) + 1e-4f);
        o.w = 0.125f * (expf(dd[i][3] - diag) + 1e-4f);
        *(float4*)&phi[((size_t)blk * 64 + r0 + i) * 64 + f0] = o;
    }
}

// ================= chunk kernels =================
__global__ __launch_bounds__(256) void chunk_local_kernel(const float* __restrict__ phiK,
                                                          const float* __restrict__ V,
                                                          float* __restrict__ kvloc,
                                                          float* __restrict__ kloc)
{
    __shared__ float ks[16*64];
    __shared__ float vs[16*64];
    const int t = threadIdx.x;
    const int chunk = blockIdx.x, bh = blockIdx.y;
    const size_t base = ((size_t)bh * SEQ + chunk * CH) * 64;
    const int f = t >> 2, c0 = t & 3;

    float acc[16];
#pragma unroll
    for (int m = 0; m < 16; m++) acc[m] = 0.f;
    float kl = 0.f;

    for (int st = 0; st < 4; st++) {
        __syncthreads();
        {
            int r = t >> 4, c4 = (t & 15) << 2;
            *(float4*)&ks[r*64 + c4] = *(const float4*)(phiK + base + (size_t)(st*16 + r)*64 + c4);
            *(float4*)&vs[r*64 + c4] = *(const float4*)(V    + base + (size_t)(st*16 + r)*64 + c4);
        }
        __syncthreads();
#pragma unroll
        for (int r = 0; r < 16; r++) {
            float kv = ks[r*64 + f];
#pragma unroll
            for (int m = 0; m < 16; m++) acc[m] += kv * vs[r*64 + c0 + 4*m];
        }
        if (t < 64) {
#pragma unroll
            for (int r = 0; r < 16; r++) kl += ks[r*64 + t];
        }
    }
    const size_t ob = ((size_t)bh * NCHUNK + chunk) * (64*64);
#pragma unroll
    for (int m = 0; m < 16; m++) kvloc[ob + (size_t)f*64 + c0 + 4*m] = acc[m];
    if (t < 64) kloc[((size_t)bh * NCHUNK + chunk) * 64 + t] = kl;
}

__global__ __launch_bounds__(256) void prefix_kernel(float* __restrict__ kvloc,
                                                     float* __restrict__ kloc)
{
    const int bh = blockIdx.x;
    const int t = threadIdx.x;
    float run[16];
#pragma unroll
    for (int m = 0; m < 16; m++) run[m] = 0.f;
    for (int c = 0; c < NCHUNK; c++) {
        const size_t b = ((size_t)bh * NCHUNK + c) * 4096;
#pragma unroll
        for (int m = 0; m < 16; m++) {
            float v = kvloc[b + t + 256*m];
            kvloc[b + t + 256*m] = run[m];
            run[m] += v;
        }
    }
    if (t < 64) {
        float rk = 0.f;
        for (int c = 0; c < NCHUNK; c++) {
            const size_t b = ((size_t)bh * NCHUNK + c) * 64 + t;
            float v = kloc[b];
            kloc[b] = rk;
            rk += v;
        }
    }
}

// chunk output + Wpost + head-transpose + bf16-split store
__global__ __launch_bounds__(256) void chunk_out_kernel(const float* __restrict__ phiQ,
                                                        const float* __restrict__ phiK,
                                                        const float* __restrict__ Vg,
                                                        const float* __restrict__ KVp,
                                                        const float* __restrict__ Kp,
                                                        const float* __restrict__ Wpost,
                                                        __nv_bfloat16* __restrict__ ahi,
                                                        __nv_bfloat16* __restrict__ alo)
{
    extern __shared__ float sm[];
    float* Qs  = sm;
    float* Ks  = Qs  + 64*PAD;
    float* Vs  = Ks  + 64*PAD;
    float* Ss  = Vs  + 64*PAD;
    float* KVs = Ss  + 64*PAD;
    float* Wps = KVs + 64*PAD;
    float* den = Wps + 64*PAD;
    float* kps = den + 64;

    const int t = threadIdx.x;
    const int chunk = blockIdx.x, bh = blockIdx.y;
    const size_t base   = ((size_t)bh * SEQ + chunk * CH) * 64;
    const size_t kvbase = ((size_t)bh * NCHUNK + chunk) * 4096;

    for (int i = t; i < 1024; i += 256) {
        int r = i >> 4, c4 = (i & 15) << 2;
        *(float4*)&Qs [r*PAD + c4] = *(const float4*)(phiQ + base   + (size_t)r*64 + c4);
        *(float4*)&Ks [r*PAD + c4] = *(const float4*)(phiK + base   + (size_t)r*64 + c4);
        *(float4*)&Vs [r*PAD + c4] = *(const float4*)(Vg   + base   + (size_t)r*64 + c4);
        *(float4*)&KVs[r*PAD + c4] = *(const float4*)(KVp  + kvbase + (size_t)r*64 + c4);
    }
    for (int i = t; i < 4096; i += 256) {
        int e = i >> 6, c = i & 63;
        Wps[c*PAD + e] = Wpost[i];
    }
    if (t < 64) kps[t] = Kp[((size_t)bh * NCHUNK + chunk) * 64 + t];
    __syncthreads();

    const int r  = t >> 2;
    const int c0 = t & 3;

    float sacc[16];
#pragma unroll
    for (int m = 0; m < 16; m++) sacc[m] = 0.f;
#pragma unroll
    for (int d = 0; d < 64; d += 4) {
        float4 q4 = *(const float4*)&Qs[r*PAD + d];
#pragma unroll
        for (int m = 0; m < 16; m++) {
            int j = c0 + 4*m;
            float4 k4 = *(const float4*)&Ks[j*PAD + d];
            sacc[m] += q4.x*k4.x + q4.y*k4.y + q4.z*k4.z + q4.w*k4.w;
        }
    }
    float rs = 0.f;
#pragma unroll
    for (int m = 0; m < 16; m++) {
        int j = c0 + 4*m;
        float sv = (j <= r) ? sacc[m] : 0.f;
        Ss[r*PAD + j] = sv;
        rs += sv;
    }
    float qk = 0.f;
#pragma unroll
    for (int m = 0; m < 16; m++) {
        int c = c0 + 4*m;
        qk += Qs[r*PAD + c] * kps[c];
    }
    float dp = rs + qk;
    dp += __shfl_xor_sync(0xffffffffu, dp, 1);
    dp += __shfl_xor_sync(0xffffffffu, dp, 2);
    if (c0 == 0) den[r] = fmaxf(dp, 1e-6f);
    __syncthreads();

    float oacc[16];
#pragma unroll
    for (int m = 0; m < 16; m++) oacc[m] = 0.f;
#pragma unroll
    for (int j = 0; j < 64; j += 4) {
        float4 s4 = *(const float4*)&Ss[r*PAD + j];
#pragma unroll
        for (int m = 0; m < 16; m++) {
            int c = c0 + 4*m;
            oacc[m] += s4.x*Vs[(j+0)*PAD + c] + s4.y*Vs[(j+1)*PAD + c]
                     + s4.z*Vs[(j+2)*PAD + c] + s4.w*Vs[(j+3)*PAD + c];
        }
    }
#pragma unroll
    for (int f = 0; f < 64; f += 4) {
        float4 q4 = *(const float4*)&Qs[r*PAD + f];
#pragma unroll
        for (int m = 0; m < 16; m++) {
            int c = c0 + 4*m;
            oacc[m] += q4.x*KVs[(f+0)*PAD + c] + q4.y*KVs[(f+1)*PAD + c]
                     + q4.z*KVs[(f+2)*PAD + c] + q4.w*KVs[(f+3)*PAD + c];
        }
    }
    const float inv = 1.0f / den[r];
#pragma unroll
    for (int m = 0; m < 16; m++) oacc[m] *= inv;
    __syncthreads();
#pragma unroll
    for (int m = 0; m < 16; m++) Ss[r*PAD + c0 + 4*m] = oacc[m];
    __syncthreads();

    float facc[16];
#pragma unroll
    for (int m = 0; m < 16; m++) facc[m] = 0.f;
#pragma unroll
    for (int c = 0; c < 64; c += 4) {
        float4 o4 = *(const float4*)&Ss[r*PAD + c];
#pragma unroll
        for (int m = 0; m < 16; m++) {
            int e = c0 + 4*m;
            facc[m] += o4.x*Wps[(c+0)*PAD + e] + o4.y*Wps[(c+1)*PAD + e]
                     + o4.z*Wps[(c+2)*PAD + e] + o4.w*Wps[(c+3)*PAD + e];
        }
    }
    const int bi = bh >> 4, hi2 = bh & 15;
    const int si = chunk * CH + r;
    const size_t ob = ((size_t)bi * SEQ + si) * DIM + hi2 * 64;
#pragma unroll
    for (int m = 0; m < 16; m++) {
        float f = facc[m];
        __nv_bfloat16 h = __float2bfloat16(f);
        ahi[ob + c0 + 4*m] = h;
        alo[ob + c0 + 4*m] = __float2bfloat16(f - __bfloat162float(h));
    }
}

// ================= launch =================
extern "C" void kernel_launch(void* const* d_in, const int* in_sizes, int n_in,
                              void* d_out, int out_size)
{
    const float* x     = (const float*)d_in[0];
    const float* Wq    = (const float*)d_in[1];
    const float* Wk    = (const float*)d_in[2];
    const float* Wv    = (const float*)d_in[3];
    const float* proj  = (const float*)d_in[4];
    const float* Wpost = (const float*)d_in[5];
    const float* Wout  = (const float*)d_in[6];
    float* out = (float*)d_out;

    float *pQ, *pK, *pV, *pphiq, *pphik, *pkv, *pks;
    __nv_bfloat16 *pxhi, *pxlo, *pahi, *palo, *pwhi, *pwlo;
    cudaGetSymbolAddress((void**)&pQ, g_Q);
    cudaGetSymbolAddress((void**)&pK, g_K);
    cudaGetSymbolAddress((void**)&pV, g_V);
    cudaGetSymbolAddress((void**)&pphiq, g_phiq);
    cudaGetSymbolAddress((void**)&pphik, g_phik);
    cudaGetSymbolAddress((void**)&pkv, g_kv);
    cudaGetSymbolAddress((void**)&pks, g_ks);
    cudaGetSymbolAddress((void**)&pxhi, g_xhi);
    cudaGetSymbolAddress((void**)&pxlo, g_xlo);
    cudaGetSymbolAddress((void**)&pahi, g_ahi);
    cudaGetSymbolAddress((void**)&palo, g_alo);
    cudaGetSymbolAddress((void**)&pwhi, g_whi);
    cudaGetSymbolAddress((void**)&pwlo, g_wlo);

    static const size_t chunk_smem = (size_t)(6*64*PAD + 128) * sizeof(float);
    cudaFuncSetAttribute(chunk_out_kernel, cudaFuncAttributeMaxDynamicSharedMemorySize,
                         (int)chunk_smem);
    static const int gemm_smem = 2 * BUFB;      // 81920 B
    cudaFuncSetAttribute(gemm_hmma_split, cudaFuncAttributeMaxDynamicSharedMemorySize, gemm_smem);

    // one fused conversion launch (x + 4 weights)
    convert_all<<<12288, 256>>>(x, Wq, Wk, Wv, Wout, pxhi, pxlo, pwhi, pwlo);

    // fused Q/K/V projection
    dim3 gqkv(24, MROWS/128);
    gemm_hmma_split<<<gqkv, 256, gemm_smem>>>(pxhi, pxlo, pwhi, pwlo, pQ, pK, pV, DIM);

    // fused feature maps
    feature_both<<<2*(ROWS/64), 256>>>(pQ, pK, proj, pphiq, pphik);

    dim3 gc(NCHUNK, NBH);            // (32, 64)
    chunk_local_kernel<<<gc, 256>>>(pphik, pV, pkv, pks);
    prefix_kernel<<<NBH, 256>>>(pkv, pks);
    chunk_out_kernel<<<gc, 256, chunk_smem>>>(pphiq, pphik, pV, pkv, pks, Wpost, pahi, palo);

    // final output projection
    dim3 gout(8, MROWS/128);
    gemm_hmma_split<<<gout, 256, gemm_smem>>>(pahi, palo, pwhi + 3*DIM*DIM, pwlo + 3*DIM*DIM,
                                              out, out, out, DIM);
}

// round 7
// speedup vs baseline: 3.3128x; 1.2638x over previous
#include <cuda_runtime.h>
#include <cuda_bf16.h>
#include <math.h>
#include <cstdint>

// Problem constants
#define BATCH 4
#define SEQ   2048
#define DIM   1024
#define HEADS 16
#define DH    64
#define NF    64
#define NBH   (BATCH*HEADS)          // 64
#define ROWS  (NBH*SEQ)              // 131072 head-rows
#define MROWS (BATCH*SEQ)            // 8192 GEMM rows
#define CH    64                     // chunk length
#define NCHUNK (SEQ/CH)              // 32
#define PAD   68

// ---------------- device scratch ----------------
__device__ float g_Q[ROWS*DH];
__device__ float g_K[ROWS*DH];
__device__ float g_V[ROWS*DH];
__device__ float g_phiq[ROWS*NF];
__device__ float g_phik[ROWS*NF];
__device__ float g_kv[NBH*NCHUNK*NF*DH];
__device__ float g_ks[NBH*NCHUNK*NF];
// bf16 split buffers
__device__ __nv_bfloat16 g_xhi[MROWS*DIM];
__device__ __nv_bfloat16 g_xlo[MROWS*DIM];
__device__ __nv_bfloat16 g_ahi[MROWS*DIM];
__device__ __nv_bfloat16 g_alo[MROWS*DIM];
__device__ __nv_bfloat16 g_whi[4*DIM*DIM];
__device__ __nv_bfloat16 g_wlo[4*DIM*DIM];

// ================= helpers =================
__device__ __forceinline__ uint32_t smem_u32(const void* p) {
    uint32_t a;
    asm("{ .reg .u64 tmp; cvta.to.shared.u64 tmp, %1; cvt.u32.u64 %0, tmp; }" : "=r"(a) : "l"(p));
    return a;
}
__device__ __forceinline__ void ldm_x4(uint32_t* r, uint32_t addr) {
    asm volatile("ldmatrix.sync.aligned.m8n8.x4.shared.b16 {%0,%1,%2,%3}, [%4];"
        : "=r"(r[0]), "=r"(r[1]), "=r"(r[2]), "=r"(r[3]) : "r"(addr));
}
__device__ __forceinline__ void mma_bf16(float* d, const uint32_t* a, const uint32_t* b) {
    asm volatile("mma.sync.aligned.m16n8k16.row.col.f32.bf16.bf16.f32 "
        "{%0,%1,%2,%3}, {%4,%5,%6,%7}, {%8,%9}, {%0,%1,%2,%3};"
        : "+f"(d[0]), "+f"(d[1]), "+f"(d[2]), "+f"(d[3])
        : "r"(a[0]), "r"(a[1]), "r"(a[2]), "r"(a[3]), "r"(b[0]), "r"(b[1]));
}
__device__ __forceinline__ void cp16(uint32_t dst, const void* src) {
    asm volatile("cp.async.cg.shared.global [%0], [%1], 16;" :: "r"(dst), "l"(src));
}
#define CP_COMMIT() asm volatile("cp.async.commit_group;" ::: "memory")
#define CP_WAIT(N)  asm volatile("cp.async.wait_group %0;" :: "n"(N) : "memory")

// ================= fused split conversion (x + 4 weights, one launch) =================
__global__ __launch_bounds__(256) void convert_all(
    const float* __restrict__ x,
    const float* __restrict__ Wq, const float* __restrict__ Wk,
    const float* __restrict__ Wv, const float* __restrict__ Wout,
    __nv_bfloat16* __restrict__ xhi, __nv_bfloat16* __restrict__ xlo,
    __nv_bfloat16* __restrict__ whi, __nv_bfloat16* __restrict__ wlo)
{
    const int b = blockIdx.x;
    const float* src;
    __nv_bfloat16 *hi, *lo;
    int i;
    if (b < 8192) {
        src = x; hi = xhi; lo = xlo;
        i = b * 256 + threadIdx.x;
    } else {
        const int wb = b - 8192;
        const int w = wb >> 10;
        const int r = wb & 1023;
        src = (w == 0) ? Wq : (w == 1) ? Wk : (w == 2) ? Wv : Wout;
        hi = whi + (size_t)w * DIM * DIM;
        lo = wlo + (size_t)w * DIM * DIM;
        i = r * 256 + threadIdx.x;
    }
    float4 v = ((const float4*)src)[i];
    __nv_bfloat16 h0 = __float2bfloat16(v.x);
    __nv_bfloat16 h1 = __float2bfloat16(v.y);
    __nv_bfloat16 h2 = __float2bfloat16(v.z);
    __nv_bfloat16 h3 = __float2bfloat16(v.w);
    __nv_bfloat16 l0 = __float2bfloat16(v.x - __bfloat162float(h0));
    __nv_bfloat16 l1 = __float2bfloat16(v.y - __bfloat162float(h1));
    __nv_bfloat16 l2 = __float2bfloat16(v.z - __bfloat162float(h2));
    __nv_bfloat16 l3 = __float2bfloat16(v.w - __bfloat162float(h3));
    __nv_bfloat162 p;
    p.x = h0; p.y = h1; ((__nv_bfloat162*)hi)[2*i]   = p;
    p.x = h2; p.y = h3; ((__nv_bfloat162*)hi)[2*i+1] = p;
    p.x = l0; p.y = l1; ((__nv_bfloat162*)lo)[2*i]   = p;
    p.x = l2; p.y = l3; ((__nv_bfloat162*)lo)[2*i+1] = p;
}

// ================= HMMA split-bf16 GEMM (unchanged from R6) =================
#define ASTR 40
#define TILE_SMEM (128*ASTR*2)
#define BUFB (4*TILE_SMEM)

__global__ __launch_bounds__(256, 2) void gemm_hmma_split(
    const __nv_bfloat16* __restrict__ Ahi, const __nv_bfloat16* __restrict__ Alo,
    const __nv_bfloat16* __restrict__ Bhi_all, const __nv_bfloat16* __restrict__ Blo_all,
    float* __restrict__ C0, float* __restrict__ C1, float* __restrict__ C2, int K)
{
    extern __shared__ char smx[];
    const int t = threadIdx.x;
    const int wid = t >> 5, lane = t & 31;
    const int wm = wid >> 2, wn = wid & 3;
    const int bm = blockIdx.y * 128;
    const int which = blockIdx.x >> 3;
    const int bn = (blockIdx.x & 7) * 128;
    const __nv_bfloat16* Bh = Bhi_all + (size_t)which * DIM * DIM;
    const __nv_bfloat16* Bl = Blo_all + (size_t)which * DIM * DIM;
    float* C = (which == 0) ? C0 : (which == 1) ? C1 : C2;

    const uint32_t smb = smem_u32(smx);
    const __nv_bfloat16* srcs[4] = {Ahi, Alo, Bh, Bl};

    float acc[4][4][4];
#pragma unroll
    for (int i = 0; i < 4; i++)
#pragma unroll
        for (int j = 0; j < 4; j++)
#pragma unroll
            for (int q = 0; q < 4; q++) acc[i][j][q] = 0.f;

    auto issue = [&](int s, int b) {
        const int k0 = s * 32;
#pragma unroll
        for (int q = 0; q < 8; q++) {
            int tile = q >> 1;
            int i = (q & 1) * 256 + t;
            int r = i >> 2, ch = i & 3;
            int rb = (tile < 2) ? bm : bn;
            cp16(smb + b * BUFB + tile * TILE_SMEM + r * 80 + ch * 16,
                 srcs[tile] + (size_t)(rb + r) * K + k0 + ch * 8);
        }
        CP_COMMIT();
    };

    auto compute = [&](int b) {
        const uint32_t Ahb = smb + b * BUFB;
        const uint32_t Alb = Ahb + TILE_SMEM;
        const uint32_t Bhb = Ahb + 2 * TILE_SMEM;
        const uint32_t Blb = Ahb + 3 * TILE_SMEM;
        const int lrA = lane & 15, kbA = lane >> 4;
        const int nrB = (lane & 7) + ((lane >> 4) << 3);
        const int kbB = (lane >> 3) & 1;
#pragma unroll
        for (int ks = 0; ks < 2; ks++) {
            uint32_t bhf[4][2], blf[4][2];
#pragma unroll
            for (int np = 0; np < 2; np++) {
                uint32_t off = (uint32_t)((wn * 32 + np * 16 + nrB) * 80 + ks * 32 + kbB * 16);
                uint32_t tmp[4];
                ldm_x4(tmp, Bhb + off);
                bhf[2*np][0] = tmp[0]; bhf[2*np][1] = tmp[1];
                bhf[2*np+1][0] = tmp[2]; bhf[2*np+1][1] = tmp[3];
                ldm_x4(tmp, Blb + off);
                blf[2*np][0] = tmp[0]; blf[2*np][1] = tmp[1];
                blf[2*np+1][0] = tmp[2]; blf[2*np+1][1] = tmp[3];
            }
#pragma unroll
            for (int ma = 0; ma < 4; ma++) {
                uint32_t ah[4], al[4];
                uint32_t off = (uint32_t)((wm * 64 + ma * 16 + lrA) * 80 + ks * 32 + kbA * 16);
                ldm_x4(ah, Ahb + off);
                ldm_x4(al, Alb + off);
#pragma unroll
                for (int na = 0; na < 4; na++) {
                    mma_bf16(acc[ma][na], ah, bhf[na]);
                    mma_bf16(acc[ma][na], ah, blf[na]);
                    mma_bf16(acc[ma][na], al, bhf[na]);
                }
            }
        }
    };

    const int S = K / 32;
    issue(0, 0);
    for (int s = 0; s < S; s++) {
        CP_WAIT(0);
        __syncthreads();
        if (s + 1 < S) issue(s + 1, (s + 1) & 1);
        compute(s & 1);
    }

    const int g = lane >> 2, tig = lane & 3;
#pragma unroll
    for (int ma = 0; ma < 4; ma++) {
        const int r0 = bm + wm * 64 + ma * 16 + g;
#pragma unroll
        for (int na = 0; na < 4; na++) {
            const int c = bn + wn * 32 + na * 8 + tig * 2;
            *(float2*)(C + (size_t)r0 * DIM + c)       = make_float2(acc[ma][na][0], acc[ma][na][1]);
            *(float2*)(C + (size_t)(r0 + 8) * DIM + c) = make_float2(acc[ma][na][2], acc[ma][na][3]);
        }
    }
}

// ================= fused feature map (unchanged) =================
__global__ __launch_bounds__(256) void feature_both(const float* __restrict__ Q,
                                                    const float* __restrict__ Kd,
                                                    const float* __restrict__ proj,
                                                    float* __restrict__ phiq,
                                                    float* __restrict__ phik)
{
    __shared__ float XsT[64*PAD];
    __shared__ float pT[64*PAD];
    const int t = threadIdx.x;
    const int nb = ROWS / 64;
    const int is_query = (blockIdx.x < nb) ? 1 : 0;
    const int blk = is_query ? blockIdx.x : blockIdx.x - nb;
    const float* X = is_query ? Q : Kd;
    float* phi = is_query ? phiq : phik;
    const size_t base = (size_t)blk * 64 * 64;

    for (int i = t; i < 4096; i += 256) { int f_ = i >> 6, d_ = i & 63; pT[d_*PAD + f_] = proj[i]; }
    for (int i = t; i < 4096; i += 256) { int r_ = i >> 6, d_ = i & 63; XsT[d_*PAD + r_] = X[base + i]; }
    __syncthreads();

    const int r0 = (t >> 4) << 2;
    const int f0 = (t & 15) << 2;
    float acc[4][4], sq[4];
#pragma unroll
    for (int i = 0; i < 4; i++) { sq[i] = 0.f;
#pragma unroll
        for (int j = 0; j < 4; j++) acc[i][j] = 0.f; }

#pragma unroll
    for (int d = 0; d < 64; d++) {
        float4 a = *(const float4*)&XsT[d*PAD + r0];
        float4 b = *(const float4*)&pT[d*PAD + f0];
        float av[4] = {a.x, a.y, a.z, a.w};
        float bv[4] = {b.x, b.y, b.z, b.w};
#pragma unroll
        for (int i = 0; i < 4; i++) {
            sq[i] += av[i] * av[i];
#pragma unroll
            for (int j = 0; j < 4; j++) acc[i][j] += av[i] * bv[j];
        }
    }
    const float dn = 0.35355339059327373f;
    float dd[4][4];
#pragma unroll
    for (int i = 0; i < 4; i++)
#pragma unroll
        for (int j = 0; j < 4; j++) dd[i][j] = dn * acc[i][j];

    if (is_query) {
#pragma unroll
        for (int i = 0; i < 4; i++) {
            float mx = fmaxf(fmaxf(dd[i][0], dd[i][1]), fmaxf(dd[i][2], dd[i][3]));
#pragma unroll
            for (int o = 8; o >= 1; o >>= 1) mx = fmaxf(mx, __shfl_xor_sync(0xffffffffu, mx, o));
#pragma unroll
            for (int j = 0; j < 4; j++) dd[i][j] -= mx;
        }
    }
#pragma unroll
    for (int i = 0; i < 4; i++) {
        const float diag = sq[i] * (1.0f / 128.0f);
        float4 o;
        o.x = 0.125f * (expf(dd[i][0] - diag) + 1e-4f);
        o.y = 0.125f * (expf(dd[i][1] - diag) + 1e-4f);
        o.z = 0.125f * (expf(dd[i][2] - diag) + 1e-4f);
        o.w = 0.125f * (expf(dd[i][3] - diag) + 1e-4f);
        *(float4*)&phi[((size_t)blk * 64 + r0 + i) * 64 + f0] = o;
    }
}

// ================= chunk_local: 4x4 register-tiled K^T V =================
__global__ __launch_bounds__(256) void chunk_local_kernel(const float* __restrict__ phiK,
                                                          const float* __restrict__ V,
                                                          float* __restrict__ kvloc,
                                                          float* __restrict__ kloc)
{
    __shared__ float ks[64*PAD];
    __shared__ float vs[64*PAD];
    const int t = threadIdx.x;
    const int chunk = blockIdx.x, bh = blockIdx.y;
    const size_t base = ((size_t)bh * SEQ + chunk * CH) * 64;

    for (int i = t; i < 1024; i += 256) {
        int r = i >> 4, c4 = (i & 15) << 2;
        *(float4*)&ks[r*PAD + c4] = *(const float4*)(phiK + base + (size_t)r*64 + c4);
        *(float4*)&vs[r*PAD + c4] = *(const float4*)(V    + base + (size_t)r*64 + c4);
    }
    __syncthreads();

    const int f0 = (t >> 4) << 2;
    const int c0 = (t & 15) << 2;
    float acc[4][4], kl[4];
#pragma unroll
    for (int i = 0; i < 4; i++) { kl[i] = 0.f;
#pragma unroll
        for (int j = 0; j < 4; j++) acc[i][j] = 0.f; }

#pragma unroll 8
    for (int r = 0; r < 64; r++) {
        float4 k4 = *(const float4*)&ks[r*PAD + f0];   // broadcast in half-warp
        float4 v4 = *(const float4*)&vs[r*PAD + c0];   // spread, conflict-free
        float kv[4] = {k4.x, k4.y, k4.z, k4.w};
        float vv[4] = {v4.x, v4.y, v4.z, v4.w};
#pragma unroll
        for (int i = 0; i < 4; i++) {
            kl[i] += kv[i];
#pragma unroll
            for (int j = 0; j < 4; j++) acc[i][j] += kv[i] * vv[j];
        }
    }
    const size_t ob = ((size_t)bh * NCHUNK + chunk) * (64*64);
#pragma unroll
    for (int i = 0; i < 4; i++)
        *(float4*)&kvloc[ob + (size_t)(f0+i)*64 + c0] =
            make_float4(acc[i][0], acc[i][1], acc[i][2], acc[i][3]);
    if ((t & 15) == 0) {
        const size_t kb = ((size_t)bh * NCHUNK + chunk) * 64 + f0;
#pragma unroll
        for (int i = 0; i < 4; i++) kloc[kb + i] = kl[i];
    }
}

// ================= prefix: parallel column-slices =================
// grid (16, NBH): block (g, bh) owns elements [g*256, g*256+256) of each 4096-wide chunk state
__global__ __launch_bounds__(256) void prefix_kernel(float* __restrict__ kvloc,
                                                     float* __restrict__ kloc)
{
    const int g = blockIdx.x, bh = blockIdx.y;
    const int t = threadIdx.x;
    const int e = g * 256 + t;
    float run = 0.f;
    for (int c = 0; c < NCHUNK; c++) {
        const size_t idx = ((size_t)bh * NCHUNK + c) * 4096 + e;
        float v = kvloc[idx];
        kvloc[idx] = run;
        run += v;
    }
    if (g == 0 && t < 64) {
        float rk = 0.f;
        for (int c = 0; c < NCHUNK; c++) {
            const size_t b = ((size_t)bh * NCHUNK + c) * 64 + t;
            float v = kloc[b];
            kloc[b] = rk;
            rk += v;
        }
    }
}

// ================= chunk_out: 4x4 register-tiled everywhere =================
__global__ __launch_bounds__(256) void chunk_out_kernel(const float* __restrict__ phiQ,
                                                        const float* __restrict__ phiK,
                                                        const float* __restrict__ Vg,
                                                        const float* __restrict__ KVp,
                                                        const float* __restrict__ Kp,
                                                        const float* __restrict__ Wpost,
                                                        __nv_bfloat16* __restrict__ ahi,
                                                        __nv_bfloat16* __restrict__ alo)
{
    extern __shared__ float sm[];
    float* QsT = sm;                 // [d][r] transposed
    float* KsT = QsT + 64*PAD;       // [d][c] transposed
    float* Vs  = KsT + 64*PAD;       // [j][c] row-major
    float* KVs = Vs  + 64*PAD;       // [f][c] row-major
    float* Ss  = KVs + 64*PAD;       // [r][j] row-major (S, then O)
    float* Wps = Ss  + 64*PAD;       // [c][e] transposed Wpost
    float* den = Wps + 64*PAD;       // 64
    float* kps = den + 64;           // 64

    const int t = threadIdx.x;
    const int chunk = blockIdx.x, bh = blockIdx.y;
    const size_t base   = ((size_t)bh * SEQ + chunk * CH) * 64;
    const size_t kvbase = ((size_t)bh * NCHUNK + chunk) * 4096;

    // transposed scalar stores for Q,K; vectorized for V,KV; Wpost transpose
    for (int i = t; i < 4096; i += 256) {
        int r = i >> 6, d = i & 63;
        QsT[d*PAD + r] = phiQ[base + i];
        KsT[d*PAD + r] = phiK[base + i];
        Wps[(i & 63)*PAD + (i >> 6)] = Wpost[i];
    }
    for (int i = t; i < 1024; i += 256) {
        int r = i >> 4, c4 = (i & 15) << 2;
        *(float4*)&Vs [r*PAD + c4] = *(const float4*)(Vg  + base   + (size_t)r*64 + c4);
        *(float4*)&KVs[r*PAD + c4] = *(const float4*)(KVp + kvbase + (size_t)r*64 + c4);
    }
    if (t < 64) kps[t] = Kp[((size_t)bh * NCHUNK + chunk) * 64 + t];
    __syncthreads();

    const int r0 = (t >> 4) << 2;    // rows (shared by 16 consecutive threads)
    const int c0 = (t & 15) << 2;    // cols

    // ---- Phase S: S = Q K^T  (+ kq = q . kprev) ----
    float sacc[4][4], kq[4];
#pragma unroll
    for (int i = 0; i < 4; i++) { kq[i] = 0.f;
#pragma unroll
        for (int j = 0; j < 4; j++) sacc[i][j] = 0.f; }
#pragma unroll 8
    for (int d = 0; d < 64; d++) {
        float4 q4 = *(const float4*)&QsT[d*PAD + r0];   // broadcast
        float4 k4 = *(const float4*)&KsT[d*PAD + c0];   // spread
        float kp = kps[d];
        float qv[4] = {q4.x, q4.y, q4.z, q4.w};
        float kv[4] = {k4.x, k4.y, k4.z, k4.w};
#pragma unroll
        for (int i = 0; i < 4; i++) {
            kq[i] += qv[i] * kp;
#pragma unroll
            for (int j = 0; j < 4; j++) sacc[i][j] += qv[i] * kv[j];
        }
    }
    // mask + rowsum + store S
    float rs[4];
#pragma unroll
    for (int i = 0; i < 4; i++) {
        const int r = r0 + i;
        float m0 = (c0+0 <= r) ? sacc[i][0] : 0.f;
        float m1 = (c0+1 <= r) ? sacc[i][1] : 0.f;
        float m2 = (c0+2 <= r) ? sacc[i][2] : 0.f;
        float m3 = (c0+3 <= r) ? sacc[i][3] : 0.f;
        *(float4*)&Ss[r*PAD + c0] = make_float4(m0, m1, m2, m3);
        rs[i] = m0 + m1 + m2 + m3;
    }
#pragma unroll
    for (int o = 8; o >= 1; o >>= 1)
#pragma unroll
        for (int i = 0; i < 4; i++) rs[i] += __shfl_xor_sync(0xffffffffu, rs[i], o);
    if ((t & 15) == 0) {
#pragma unroll
        for (int i = 0; i < 4; i++) den[r0 + i] = fmaxf(rs[i] + kq[i], 1e-6f);
    }
    __syncthreads();

    // ---- Phase O: O = S V + Q KVprev ----
    float oacc[4][4];
#pragma unroll
    for (int i = 0; i < 4; i++)
#pragma unroll
        for (int j = 0; j < 4; j++) oacc[i][j] = 0.f;
#pragma unroll 4
    for (int j0 = 0; j0 < 64; j0 += 4) {
        float4 s4[4], v4[4];
#pragma unroll
        for (int i = 0; i < 4; i++)  s4[i]  = *(const float4*)&Ss[(r0+i)*PAD + j0];  // broadcast
#pragma unroll
        for (int jj = 0; jj < 4; jj++) v4[jj] = *(const float4*)&Vs[(j0+jj)*PAD + c0]; // spread
#pragma unroll
        for (int i = 0; i < 4; i++) {
            float sv[4] = {s4[i].x, s4[i].y, s4[i].z, s4[i].w};
#pragma unroll
            for (int jj = 0; jj < 4; jj++) {
                oacc[i][0] += sv[jj] * (&v4[jj].x)[0];
                oacc[i][1] += sv[jj] * (&v4[jj].x)[1];
                oacc[i][2] += sv[jj] * (&v4[jj].x)[2];
                oacc[i][3] += sv[jj] * (&v4[jj].x)[3];
            }
        }
    }
#pragma unroll 4
    for (int f0 = 0; f0 < 64; f0 += 4) {
        float4 q4[4], kv4[4];
#pragma unroll
        for (int jj = 0; jj < 4; jj++) {
            q4[jj]  = *(const float4*)&QsT[(f0+jj)*PAD + r0];   // broadcast
            kv4[jj] = *(const float4*)&KVs[(f0+jj)*PAD + c0];   // spread
        }
#pragma unroll
        for (int jj = 0; jj < 4; jj++) {
            float qv[4] = {q4[jj].x, q4[jj].y, q4[jj].z, q4[jj].w};
#pragma unroll
            for (int i = 0; i < 4; i++) {
                oacc[i][0] += qv[i] * (&kv4[jj].x)[0];
                oacc[i][1] += qv[i] * (&kv4[jj].x)[1];
                oacc[i][2] += qv[i] * (&kv4[jj].x)[2];
                oacc[i][3] += qv[i] * (&kv4[jj].x)[3];
            }
        }
    }
#pragma unroll
    for (int i = 0; i < 4; i++) {
        const float inv = 1.0f / den[r0 + i];
#pragma unroll
        for (int j = 0; j < 4; j++) oacc[i][j] *= inv;
    }
    __syncthreads();
#pragma unroll
    for (int i = 0; i < 4; i++)
        *(float4*)&Ss[(r0+i)*PAD + c0] = make_float4(oacc[i][0], oacc[i][1], oacc[i][2], oacc[i][3]);
    __syncthreads();

    // ---- Phase W: F = O @ Wpost^T ----
    float facc[4][4];
#pragma unroll
    for (int i = 0; i < 4; i++)
#pragma unroll
        for (int j = 0; j < 4; j++) facc[i][j] = 0.f;
#pragma unroll 4
    for (int cg = 0; cg < 64; cg += 4) {
        float4 o4[4], w4[4];
#pragma unroll
        for (int i = 0; i < 4; i++)   o4[i]  = *(const float4*)&Ss[(r0+i)*PAD + cg];   // broadcast
#pragma unroll
        for (int jj = 0; jj < 4; jj++) w4[jj] = *(const float4*)&Wps[(cg+jj)*PAD + c0]; // spread
#pragma unroll
        for (int i = 0; i < 4; i++) {
            float ov[4] = {o4[i].x, o4[i].y, o4[i].z, o4[i].w};
#pragma unroll
            for (int jj = 0; jj < 4; jj++) {
                facc[i][0] += ov[jj] * (&w4[jj].x)[0];
                facc[i][1] += ov[jj] * (&w4[jj].x)[1];
                facc[i][2] += ov[jj] * (&w4[jj].x)[2];
                facc[i][3] += ov[jj] * (&w4[jj].x)[3];
            }
        }
    }

    // ---- store with head-transpose + bf16 split ----
    const int bi = bh >> 4, hi2 = bh & 15;
#pragma unroll
    for (int i = 0; i < 4; i++) {
        const int si = chunk * CH + r0 + i;
        const size_t ob = ((size_t)bi * SEQ + si) * DIM + hi2 * 64 + c0;
        __nv_bfloat162 hp[2], lp[2];
#pragma unroll
        for (int j = 0; j < 2; j++) {
            float fa = facc[i][2*j], fb = facc[i][2*j+1];
            __nv_bfloat16 ha = __float2bfloat16(fa);
            __nv_bfloat16 hb = __float2bfloat16(fb);
            hp[j].x = ha; hp[j].y = hb;
            lp[j].x = __float2bfloat16(fa - __bfloat162float(ha));
            lp[j].y = __float2bfloat16(fb - __bfloat162float(hb));
        }
        *(float2*)(ahi + ob) = *(float2*)hp;
        *(float2*)(alo + ob) = *(float2*)lp;
    }
}

// ================= launch =================
extern "C" void kernel_launch(void* const* d_in, const int* in_sizes, int n_in,
                              void* d_out, int out_size)
{
    const float* x     = (const float*)d_in[0];
    const float* Wq    = (const float*)d_in[1];
    const float* Wk    = (const float*)d_in[2];
    const float* Wv    = (const float*)d_in[3];
    const float* proj  = (const float*)d_in[4];
    const float* Wpost = (const float*)d_in[5];
    const float* Wout  = (const float*)d_in[6];
    float* out = (float*)d_out;

    float *pQ, *pK, *pV, *pphiq, *pphik, *pkv, *pks;
    __nv_bfloat16 *pxhi, *pxlo, *pahi, *palo, *pwhi, *pwlo;
    cudaGetSymbolAddress((void**)&pQ, g_Q);
    cudaGetSymbolAddress((void**)&pK, g_K);
    cudaGetSymbolAddress((void**)&pV, g_V);
    cudaGetSymbolAddress((void**)&pphiq, g_phiq);
    cudaGetSymbolAddress((void**)&pphik, g_phik);
    cudaGetSymbolAddress((void**)&pkv, g_kv);
    cudaGetSymbolAddress((void**)&pks, g_ks);
    cudaGetSymbolAddress((void**)&pxhi, g_xhi);
    cudaGetSymbolAddress((void**)&pxlo, g_xlo);
    cudaGetSymbolAddress((void**)&pahi, g_ahi);
    cudaGetSymbolAddress((void**)&palo, g_alo);
    cudaGetSymbolAddress((void**)&pwhi, g_whi);
    cudaGetSymbolAddress((void**)&pwlo, g_wlo);

    static const size_t chunk_smem = (size_t)(6*64*PAD + 128) * sizeof(float);
    cudaFuncSetAttribute(chunk_out_kernel, cudaFuncAttributeMaxDynamicSharedMemorySize,
                         (int)chunk_smem);
    static const int gemm_smem = 2 * BUFB;
    cudaFuncSetAttribute(gemm_hmma_split, cudaFuncAttributeMaxDynamicSharedMemorySize, gemm_smem);

    convert_all<<<12288, 256>>>(x, Wq, Wk, Wv, Wout, pxhi, pxlo, pwhi, pwlo);

    dim3 gqkv(24, MROWS/128);
    gemm_hmma_split<<<gqkv, 256, gemm_smem>>>(pxhi, pxlo, pwhi, pwlo, pQ, pK, pV, DIM);

    feature_both<<<2*(ROWS/64), 256>>>(pQ, pK, proj, pphiq, pphik);

    dim3 gc(NCHUNK, NBH);
    chunk_local_kernel<<<gc, 256>>>(pphik, pV, pkv, pks);
    dim3 gp(16, NBH);
    prefix_kernel<<<gp, 256>>>(pkv, pks);
    chunk_out_kernel<<<gc, 256, chunk_smem>>>(pphiq, pphik, pV, pkv, pks, Wpost, pahi, palo);

    dim3 gout(8, MROWS/128);
    gemm_hmma_split<<<gout, 256, gemm_smem>>>(pahi, palo, pwhi + 3*DIM*DIM, pwlo + 3*DIM*DIM,
                                              out, out, out, DIM);
}